// round 11
// baseline (speedup 1.0000x reference)
#include <cuda_runtime.h>
#include <cstdint>

#define BB 8
#define MM 32
#define N0 25600
#define N1 6400
#define N2 1600
#define NTOT 33600
#define TOPKK 10
#define NB 296               // 2 blocks/SM on 148 SMs (GB300 has 152 -> all resident)
#define NTH 256
#define TOTTHR (NB * NTH)
#define SP_TOT 672000        // 80*HW/4 float4 per image
#define S0 512000
#define S1 128000
#define FG_MAX 2560

// ---------------- scratch ----------------
__device__ float4 g_pb[BB * NTOT];
__device__ float4 g_lse[BB * NTOT];
__device__ unsigned long long g_best[BB * NTOT];
__device__ double g_sp_part[BB * NB];
__device__ int g_fglist[FG_MAX];
__device__ int g_fgtot;
__device__ int g_fgcnt[BB];
__device__ float g_box[BB], g_dfl[BB], g_clspos[BB];
__device__ unsigned g_bar_count;   // zero-init
__device__ unsigned g_bar_gen;     // monotonic across replays

// ---------------- helpers ----------------
__device__ __forceinline__ float ciou_f(float b1x1, float b1y1, float b1x2, float b1y2,
                                        float b2x1, float b2y1, float b2x2, float b2y2) {
    const float eps = 1e-7f;
    float w1 = b1x2 - b1x1, h1 = b1y2 - b1y1;
    float w2 = b2x2 - b2x1, h2 = b2y2 - b2y1;
    float iw = fminf(b1x2, b2x2) - fmaxf(b1x1, b2x1);
    float ih = fminf(b1y2, b2y2) - fmaxf(b1y1, b2y1);
    float inter = fmaxf(iw, 0.f) * fmaxf(ih, 0.f);
    float uni = w1 * h1 + w2 * h2 - inter + eps;
    float iou = inter / uni;
    float cw = fmaxf(b1x2, b2x2) - fminf(b1x1, b2x1);
    float ch = fmaxf(b1y2, b2y2) - fminf(b1y1, b2y1);
    float c2 = cw * cw + ch * ch + eps;
    float dx = b2x1 + b2x2 - b1x1 - b1x2;
    float dy = b2y1 + b2y2 - b1y1 - b1y2;
    float rho2 = (dx * dx + dy * dy) * 0.25f;
    float dat = atanf(w2 / (h2 + eps)) - atanf(w1 / (h1 + eps));
    float v = 0.4052847345693511f * dat * dat;
    float alpha = v / (v - iou + (1.f + eps));
    return iou - (rho2 / c2 + v * alpha);
}

__device__ __forceinline__ unsigned long long umax64(unsigned long long a, unsigned long long b) {
    return a > b ? a : b;
}

__device__ __forceinline__ unsigned long long warp_max64(unsigned long long v) {
#pragma unroll
    for (int d = 16; d > 0; d >>= 1)
        v = umax64(v, __shfl_down_sync(0xffffffffu, v, d));
    return v;
}

// sense-reversal grid barrier (gen monotonic -> replay-safe).
// gen can only advance via OUR count increment, so reading gen before the
// increment is race-free; at most one bump can occur before we observe it.
__device__ __forceinline__ void gsync() {
    __syncthreads();
    if (threadIdx.x == 0) {
        __threadfence();
        unsigned gen = atomicAdd(&g_bar_gen, 0u);
        unsigned old = atomicAdd(&g_bar_count, 1u);
        if (old == NB - 1) {
            atomicExch(&g_bar_count, 0u);
            __threadfence();
            atomicAdd(&g_bar_gen, 1u);
        } else {
            while (atomicAdd(&g_bar_gen, 0u) == gen) __nanosleep(64);
        }
        __threadfence();
    }
    __syncthreads();
}

__device__ __forceinline__ void level_of(int n, const float* p0, const float* p1,
                                         const float* p2, const float* st3,
                                         const float*& p, int& HW, int& W, int& q, float& st) {
    if (n < N0)            { p = p0; HW = N0; W = 160; q = n;             st = st3[0]; }
    else if (n < N0 + N1)  { p = p1; HW = N1; W = 80;  q = n - N0;        st = st3[1]; }
    else                   { p = p2; HW = N2; W = 40;  q = n - (N0 + N1); st = st3[2]; }
}

// =================== THE fused persistent kernel ===================
__global__ void __launch_bounds__(NTH, 2) k_fused(
        const float* __restrict__ p0, const float* __restrict__ p1,
        const float* __restrict__ p2,
        const float* __restrict__ gt_boxes, const int* __restrict__ gt_labels,
        const float* __restrict__ strides, float* __restrict__ out) {
    int tid = threadIdx.x;
    int gid = blockIdx.x * NTH + tid;
    float st3[3] = {strides[0], strides[1], strides[2]};

    __shared__ unsigned long long sh_keys[NTH * TOPKK];   // assign top-k pool
    __shared__ double sred[NTH];                          // softplus reduce
    __shared__ unsigned long long sh_w[8], sh_best;
    __shared__ float sh_fw[8], sh_cmax;

    // ---------------- phase A: init + sparse decode ----------------
    if (blockIdx.x == 0 && tid == 0) {
        g_fgtot = 0;
#pragma unroll
        for (int b = 0; b < BB; b++) { g_fgcnt[b] = 0; g_box[b] = 0.f; g_dfl[b] = 0.f; g_clspos[b] = 0.f; }
    }
    const float4* gtb4 = (const float4*)gt_boxes;
    for (int idx = gid; idx < BB * NTOT; idx += TOTTHR) {
        int b = idx / NTOT, n = idx - b * NTOT;
        const float* p; int HW, W, q; float st;
        level_of(n, p0, p1, p2, st3, p, HW, W, q, st);
        int qy = q / W;
        float ax = (float)(q - qy * W) + 0.5f;
        float ay = (float)qy + 0.5f;

        float axi = ax * st, ayi = ay * st;
        bool inside = false;
        for (int m = 0; m < MM; m++) {
            float4 g = __ldg(&gtb4[b * MM + m]);
            if (axi >= g.x && axi <= g.z && ayi >= g.y && ayi <= g.w) { inside = true; break; }
        }
        if (!inside) continue;

        const float* pb = p + (size_t)b * 144 * HW + q;
        float dist[4], lsev[4];
#pragma unroll
        for (int k = 0; k < 4; k++) {
            float se = 0.f, sw = 0.f;
#pragma unroll
            for (int r = 0; r < 16; r++) {
                float e = __expf(pb[(size_t)(k * 16 + r) * HW]);
                se += e; sw = fmaf(e, (float)r, sw);
            }
            dist[k] = sw / se;
            lsev[k] = __logf(se);
        }
        float4 o;
        o.x = (ax - dist[0]) * st;
        o.y = (ay - dist[1]) * st;
        o.z = (ax + dist[2]) * st;
        o.w = (ay + dist[3]) * st;
        g_pb[idx] = o;
        g_lse[idx] = make_float4(lsev[0], lsev[1], lsev[2], lsev[3]);
        g_best[idx] = 0xFFFFFFFFull;   // sentinel
    }
    gsync();

    // ---------------- phase B: assigner (blocks 0..255 = one per (b,m)) ----------------
    if (blockIdx.x < BB * MM) {
        int b = blockIdx.x >> 5, m = blockIdx.x & 31;
        int wid = tid >> 5, lid = tid & 31;

        float gx1 = gt_boxes[(b * MM + m) * 4 + 0];
        float gy1 = gt_boxes[(b * MM + m) * 4 + 1];
        float gx2 = gt_boxes[(b * MM + m) * 4 + 2];
        float gy2 = gt_boxes[(b * MM + m) * 4 + 3];
        int label = gt_labels[b * MM + m];

        float tv[TOPKK]; int tn[TOPKK];
#pragma unroll
        for (int jj = 0; jj < TOPKK; jj++) { tv[jj] = 0.f; tn[jj] = 0x7FFFFFFF; }
        float cmax = 0.f;

#pragma unroll
        for (int lvl = 0; lvl < 3; lvl++) {
            const float* p; int HW, W, noff; float st;
            if (lvl == 0)      { p = p0; HW = N0; W = 160; noff = 0;       st = st3[0]; }
            else if (lvl == 1) { p = p1; HW = N1; W = 80;  noff = N0;      st = st3[1]; }
            else               { p = p2; HW = N2; W = 40;  noff = N0 + N1; st = st3[2]; }

            float inv = 1.f / st;
            int x0 = max(0, (int)(gx1 * inv - 0.5f) - 1);
            int x1 = min(W - 1, (int)(gx2 * inv - 0.5f) + 1);
            int y0 = max(0, (int)(gy1 * inv - 0.5f) - 1);
            int y1 = min(W - 1, (int)(gy2 * inv - 0.5f) + 1);
            int rw = x1 - x0 + 1, rh = y1 - y0 + 1;
            if (rw <= 0 || rh <= 0) continue;
            int tot = rw * rh;
            const float* pcl = p + ((size_t)b * 144 + 64 + label) * HW;

            for (int i = tid; i < tot; i += NTH) {
                int qx = x0 + i % rw;
                int qy = y0 + i / rw;
                float ax = ((float)qx + 0.5f) * st;
                float ay = ((float)qy + 0.5f) * st;
                if (ax < gx1 || ax > gx2 || ay < gy1 || ay > gy2) continue;
                int q = qy * W + qx;
                int n = noff + q;
                float4 pbv = g_pb[b * NTOT + n];
                float iou = fmaxf(ciou_f(pbv.x, pbv.y, pbv.z, pbv.w, gx1, gy1, gx2, gy2), 0.f);
                float ps = 1.f / (1.f + __expf(-pcl[q]));
                float i2 = iou * iou;
                float align = ps * (i2 * i2 * i2);
                cmax = fmaxf(cmax, align);
                if (iou > 0.1f && align > 0.f &&
                    ((align > tv[TOPKK - 1]) ||
                     (align == tv[TOPKK - 1] && n < tn[TOPKK - 1]))) {
                    float cv = align; int cn = n;
#pragma unroll
                    for (int jj = 0; jj < TOPKK; jj++) {
                        bool bt = (cv > tv[jj]) || (cv == tv[jj] && cn < tn[jj]);
                        float nv = bt ? cv : tv[jj];  int nn = bt ? cn : tn[jj];
                        cv = bt ? tv[jj] : cv;        cn = bt ? tn[jj] : cn;
                        tv[jj] = nv;                  tn[jj] = nn;
                    }
                }
            }
        }

        // column max (raw align, pre-mask)
#pragma unroll
        for (int d = 16; d > 0; d >>= 1)
            cmax = fmaxf(cmax, __shfl_down_sync(0xffffffffu, cmax, d));
        if (lid == 0) sh_fw[wid] = cmax;
        __syncthreads();
        if (tid == 0) {
            float c = sh_fw[0];
#pragma unroll
            for (int w = 1; w < 8; w++) c = fmaxf(c, sh_fw[w]);
            sh_cmax = c;
        }
#pragma unroll
        for (int jj = 0; jj < TOPKK; jj++) {
            unsigned long long key = 0ull;
            if (tv[jj] > 0.f)
                key = ((unsigned long long)__float_as_uint(tv[jj]) << 32) |
                      (unsigned long long)(0xFFFFFFFFu - (unsigned)tn[jj]);
            sh_keys[tid * TOPKK + jj] = key;
        }
        __syncthreads();
        float colmax = sh_cmax;

        for (int iter = 0; iter < TOPKK; iter++) {
            unsigned long long loc = 0ull;
#pragma unroll
            for (int jj = 0; jj < TOPKK; jj++)
                loc = umax64(loc, sh_keys[tid + jj * NTH]);
            loc = warp_max64(loc);
            if (lid == 0) sh_w[wid] = loc;
            __syncthreads();
            if (tid == 0) {
                unsigned long long v = sh_w[0];
#pragma unroll
                for (int w = 1; w < 8; w++) v = umax64(v, sh_w[w]);
                sh_best = v;
            }
            __syncthreads();
            unsigned long long bestk = sh_best;
            if (bestk == 0ull) break;
#pragma unroll
            for (int jj = 0; jj < TOPKK; jj++)
                if (sh_keys[tid * TOPKK + jj] == bestk) sh_keys[tid * TOPKK + jj] = 0ull;
            if (tid == 0) {
                float val = __uint_as_float((unsigned)(bestk >> 32));
                int n = (int)(0xFFFFFFFFu - (unsigned)(bestk & 0xFFFFFFFFull));
                float norm = val / (colmax + 1e-9f);
                unsigned long long okey =
                    ((unsigned long long)__float_as_uint(norm) << 32) |
                    (unsigned long long)(0xFFFFFFFFu - (unsigned)m);
                int gidx = b * NTOT + n;
                unsigned long long old = atomicMax(&g_best[gidx], okey);
                if (old == 0xFFFFFFFFull) {     // first writer -> compaction
                    atomicAdd(&g_fgcnt[b], 1);
                    int pos = atomicAdd(&g_fgtot, 1);
                    g_fglist[pos] = gidx;
                }
            }
            __syncthreads();
        }
    }
    gsync();

    // ---------------- phase C1: fg losses (grid-stride over compacted list) ----------------
    int fgtot = g_fgtot;
    for (int i = gid; i < fgtot; i += TOTTHR) {
        int idx = g_fglist[i];
        unsigned long long key = g_best[idx];
        float score = __uint_as_float((unsigned)(key >> 32));
        int b = idx / NTOT, n = idx - (idx / NTOT) * NTOT;
        int m = (int)(0xFFFFFFFFu - (unsigned)(key & 0xFFFFFFFFull));

        float4 g = __ldg(&gtb4[b * MM + m]);
        int label = gt_labels[b * MM + m];

        const float* p; int HW, W, q; float st;
        level_of(n, p0, p1, p2, st3, p, HW, W, q, st);
        int qy = q / W;
        float ax = (float)(q - qy * W) + 0.5f;
        float ay = (float)qy + 0.5f;

        float4 pbv = g_pb[idx];
        float4 lse = g_lse[idx];
        float boxl = 1.f - ciou_f(pbv.x, pbv.y, pbv.z, pbv.w, g.x, g.y, g.z, g.w);

        float t0 = fminf(fmaxf(ax - g.x / st, 0.f), 14.99f);
        float t1 = fminf(fmaxf(ay - g.y / st, 0.f), 14.99f);
        float t2 = fminf(fmaxf(g.z / st - ax, 0.f), 14.99f);
        float t3 = fminf(fmaxf(g.w / st - ay, 0.f), 14.99f);
        int l0 = (int)t0, l1 = (int)t1, l2 = (int)t2, l3 = (int)t3;
        int r0 = min(l0 + 1, 15), r1 = min(l1 + 1, 15), r2 = min(l2 + 1, 15), r3 = min(l3 + 1, 15);

        const float* base = p + (size_t)b * 144 * HW + q;
        float xl0 = base[(size_t)l0 * HW];
        float xr0 = base[(size_t)r0 * HW];
        float xl1 = base[(size_t)(16 + l1) * HW];
        float xr1 = base[(size_t)(16 + r1) * HW];
        float xl2 = base[(size_t)(32 + l2) * HW];
        float xr2 = base[(size_t)(32 + r2) * HW];
        float xl3 = base[(size_t)(48 + l3) * HW];
        float xr3 = base[(size_t)(48 + r3) * HW];
        float pcv = base[(size_t)(64 + label) * HW];

        float dfl =
            ((float)r0 - t0) * (lse.x - xl0) + (t0 - (float)l0) * (lse.x - xr0) +
            ((float)r1 - t1) * (lse.y - xl1) + (t1 - (float)l1) * (lse.y - xr1) +
            ((float)r2 - t2) * (lse.z - xl2) + (t2 - (float)l2) * (lse.z - xr2) +
            ((float)r3 - t3) * (lse.w - xl3) + (t3 - (float)l3) * (lse.w - xr3);

        atomicAdd(&g_box[b], boxl);
        atomicAdd(&g_dfl[b], dfl);
        atomicAdd(&g_clspos[b], pcv * score);
    }

    // ---------------- phase C2: softplus over cls logits (per image) ----------------
    for (int b = 0; b < BB; b++) {
        const float4* f40 = (const float4*)(p0 + ((size_t)b * 144 + 64) * N0);
        const float4* f41 = (const float4*)(p1 + ((size_t)b * 144 + 64) * N1);
        const float4* f42 = (const float4*)(p2 + ((size_t)b * 144 + 64) * N2);
        float acc = 0.f;
        float P0 = 1.f, P1 = 1.f, P2 = 1.f, P3 = 1.f;
        int cnt = 0;
        for (int i = gid; i < SP_TOT; i += TOTTHR) {
            float4 v;
            if (i < S0)           v = f40[i];
            else if (i < S0 + S1) v = f41[i - S0];
            else                  v = f42[i - S0 - S1];
            float e0 = __expf(v.x), e1 = __expf(v.y), e2 = __expf(v.z), e3 = __expf(v.w);
            P0 = fmaf(P0, e0, P0);   // P *= (1 + e)
            P1 = fmaf(P1, e1, P1);
            P2 = fmaf(P2, e2, P2);
            P3 = fmaf(P3, e3, P3);
            if ((++cnt & 7) == 0) {  // flush every 32 elems; factors <= 1+e^~7
                acc += __logf((P0 * P1) * (P2 * P3));
                P0 = P1 = P2 = P3 = 1.f;
            }
        }
        acc += __logf((P0 * P1) * (P2 * P3));

        sred[tid] = (double)acc;
        __syncthreads();
        for (int s = NTH / 2; s > 0; s >>= 1) {
            if (tid < s) sred[tid] += sred[tid + s];
            __syncthreads();
        }
        if (tid == 0) g_sp_part[b * NB + blockIdx.x] = sred[0];
        __syncthreads();
    }
    gsync();

    // ---------------- phase D: final combine (block 0 only) ----------------
    if (blockIdx.x == 0) {
        int w = tid >> 5, l = tid & 31;
        __shared__ double s8[8];
        if (w < 8) {
            double sp = 0.0;
            for (int j = l; j < NB; j += 32) sp += g_sp_part[w * NB + j];
#pragma unroll
            for (int d = 16; d > 0; d >>= 1) sp += __shfl_down_sync(0xffffffffu, sp, d);
            if (l == 0) {
                int cntb = g_fgcnt[w];
                double has = cntb > 0 ? 1.0 : 0.0;
                double nf = cntb > 0 ? (double)cntb : 1.0;
                double bl = (double)g_box[w] / nf;
                double dl = (double)g_dfl[w] / (nf * 4.0);
                double cl = (sp - (double)g_clspos[w]) / (double)NTOT;
                s8[w] = (7.5 * bl + 0.5 * cl + 1.5 * dl) * has;
            }
        }
        __syncthreads();
        if (tid == 0) {
            double total = 0.0;
#pragma unroll
            for (int b = 0; b < BB; b++) total += s8[b];
            out[0] = (float)total;
        }
    }
}

// ---------------- launch: ONE kernel ----------------
extern "C" void kernel_launch(void* const* d_in, const int* in_sizes, int n_in,
                              void* d_out, int out_size) {
    const float* p0 = (const float*)d_in[0];
    const float* p1 = (const float*)d_in[1];
    const float* p2 = (const float*)d_in[2];
    const float* gtb = (const float*)d_in[3];
    const int* gtl = (const int*)d_in[4];
    const float* strides = (const float*)d_in[5];
    float* out = (float*)d_out;

    k_fused<<<NB, NTH>>>(p0, p1, p2, gtb, gtl, strides, out);
}

// round 12
// speedup vs baseline: 1.0300x; 1.0300x over previous
#include <cuda_runtime.h>
#include <cstdint>

#define BB 8
#define MM 32
#define N0 25600
#define N1 6400
#define N2 1600
#define NTOT 33600
#define TOPKK 10
#define QTOT 8400            // NTOT/4 float4-anchor groups per image
#define DEC_BLK 33           // ceil(8400/256)
#define SP_BLK 128           // softplus blocks per image
#define S0 512000            // 80*25600/4 float4 per image
#define S1 128000
#define SP_TOT 672000
#define FG_MAX 2560
#define FG_BLK 20            // 2560 threads / 128

// ---------------- scratch ----------------
__device__ float4 g_pb[BB * NTOT];                 // decoded pred boxes (in-rect only)
__device__ float4 g_lse[BB * NTOT];                // per-side log-sum-exp (in-rect only)
__device__ unsigned long long g_best[BB * NTOT];   // (score<<32 | ~m); in-rect only
__device__ double g_sp_part[BB * SP_BLK];
__device__ int g_fglist[FG_MAX];
__device__ int g_fgtot;
__device__ int g_fgcnt[BB];
__device__ float g_box[BB], g_dfl[BB], g_clspos[BB];
__device__ unsigned g_done;

// ---------------- helpers ----------------
__device__ __forceinline__ float ciou_f(float b1x1, float b1y1, float b1x2, float b1y2,
                                        float b2x1, float b2y1, float b2x2, float b2y2) {
    const float eps = 1e-7f;
    float w1 = b1x2 - b1x1, h1 = b1y2 - b1y1;
    float w2 = b2x2 - b2x1, h2 = b2y2 - b2y1;
    float iw = fminf(b1x2, b2x2) - fmaxf(b1x1, b2x1);
    float ih = fminf(b1y2, b2y2) - fmaxf(b1y1, b2y1);
    float inter = fmaxf(iw, 0.f) * fmaxf(ih, 0.f);
    float uni = w1 * h1 + w2 * h2 - inter + eps;
    float iou = inter / uni;
    float cw = fmaxf(b1x2, b2x2) - fminf(b1x1, b2x1);
    float ch = fmaxf(b1y2, b2y2) - fminf(b1y1, b2y1);
    float c2 = cw * cw + ch * ch + eps;
    float dx = b2x1 + b2x2 - b1x1 - b1x2;
    float dy = b2y1 + b2y2 - b1y1 - b1y2;
    float rho2 = (dx * dx + dy * dy) * 0.25f;
    float dat = atanf(w2 / (h2 + eps)) - atanf(w1 / (h1 + eps));
    float v = 0.4052847345693511f * dat * dat;
    float alpha = v / (v - iou + (1.f + eps));
    return iou - (rho2 / c2 + v * alpha);
}

__device__ __forceinline__ unsigned long long umax64(unsigned long long a, unsigned long long b) {
    return a > b ? a : b;
}

__device__ __forceinline__ unsigned long long warp_max64(unsigned long long v) {
#pragma unroll
    for (int d = 16; d > 0; d >>= 1)
        v = umax64(v, __shfl_down_sync(0xffffffffu, v, d));
    return v;
}

// ============ k_main: ONE wide kernel = sparse decode blocks + softplus blocks ==========
__global__ void __launch_bounds__(256) k_main(
        const float* __restrict__ p0, const float* __restrict__ p1,
        const float* __restrict__ p2, const float* __restrict__ gt_boxes,
        const float* __restrict__ strides) {
    int b = blockIdx.y;
    int tid = threadIdx.x;

    if (blockIdx.x == 0 && tid == 0) {
        g_fgcnt[b] = 0; g_box[b] = 0.f; g_dfl[b] = 0.f; g_clspos[b] = 0.f;
        if (b == 0) { g_done = 0u; g_fgtot = 0; }
    }

    if (blockIdx.x < DEC_BLK) {
        // ------- sparse decode: 4 anchors per thread (float4 channel loads) -------
        __shared__ float4 sgt[MM];
        if (tid < MM) sgt[tid] = ((const float4*)gt_boxes)[b * MM + tid];
        __syncthreads();

        int j = blockIdx.x * 256 + tid;
        if (j >= QTOT) return;
        const float* p; int HW, W, q4, noff; float st;
        if (j < 6400)      { p = p0; HW = N0; W = 160; q4 = j;        noff = 0;       st = strides[0]; }
        else if (j < 8000) { p = p1; HW = N1; W = 80;  q4 = j - 6400; noff = N0;      st = strides[1]; }
        else               { p = p2; HW = N2; W = 40;  q4 = j - 8000; noff = N0 + N1; st = strides[2]; }
        int q = q4 * 4;
        int qy = q / W;
        float ay = (float)qy + 0.5f;
        float ax = (float)(q - qy * W) + 0.5f;   // anchors ax .. ax+3 (same row: W % 4 == 0)

        // in-rect test for the 4-anchor group (inclusive; superset of assign's reads)
        float ayi = ay * st;
        float a0 = ax * st, a3 = (ax + 3.f) * st;
        bool inside = false;
        for (int m = 0; m < MM; m++) {
            float4 g = sgt[m];
            if (ayi >= g.y && ayi <= g.w && a3 >= g.x && a0 <= g.z) { inside = true; break; }
        }
        if (!inside) return;

        const float* pb = p + (size_t)b * 144 * HW + q;
        float4 out[4]; float4 lse[4];
#pragma unroll
        for (int k = 0; k < 4; k++) {
            float se0 = 0.f, se1 = 0.f, se2 = 0.f, se3 = 0.f;
            float sw0 = 0.f, sw1 = 0.f, sw2 = 0.f, sw3 = 0.f;
#pragma unroll
            for (int r = 0; r < 16; r++) {
                float4 v = *(const float4*)(pb + (size_t)(k * 16 + r) * HW);
                float e0 = __expf(v.x), e1 = __expf(v.y), e2 = __expf(v.z), e3 = __expf(v.w);
                float fr = (float)r;
                se0 += e0; sw0 = fmaf(e0, fr, sw0);
                se1 += e1; sw1 = fmaf(e1, fr, sw1);
                se2 += e2; sw2 = fmaf(e2, fr, sw2);
                se3 += e3; sw3 = fmaf(e3, fr, sw3);
            }
            float d0 = sw0 / se0, d1 = sw1 / se1, d2 = sw2 / se2, d3 = sw3 / se3;
            float l0 = __logf(se0), l1 = __logf(se1), l2 = __logf(se2), l3 = __logf(se3);
            if (k == 0) {
                out[0].x = (ax - d0) * st;       out[1].x = (ax + 1.f - d1) * st;
                out[2].x = (ax + 2.f - d2) * st; out[3].x = (ax + 3.f - d3) * st;
                lse[0].x = l0; lse[1].x = l1; lse[2].x = l2; lse[3].x = l3;
            }
            if (k == 1) {
                out[0].y = (ay - d0) * st; out[1].y = (ay - d1) * st;
                out[2].y = (ay - d2) * st; out[3].y = (ay - d3) * st;
                lse[0].y = l0; lse[1].y = l1; lse[2].y = l2; lse[3].y = l3;
            }
            if (k == 2) {
                out[0].z = (ax + d0) * st;       out[1].z = (ax + 1.f + d1) * st;
                out[2].z = (ax + 2.f + d2) * st; out[3].z = (ax + 3.f + d3) * st;
                lse[0].z = l0; lse[1].z = l1; lse[2].z = l2; lse[3].z = l3;
            }
            if (k == 3) {
                out[0].w = (ay + d0) * st; out[1].w = (ay + d1) * st;
                out[2].w = (ay + d2) * st; out[3].w = (ay + d3) * st;
                lse[0].w = l0; lse[1].w = l1; lse[2].w = l2; lse[3].w = l3;
            }
        }
        int base = b * NTOT + noff + q;
#pragma unroll
        for (int a = 0; a < 4; a++) {
            g_pb[base + a] = out[a];
            g_lse[base + a] = lse[a];
            g_best[base + a] = 0xFFFFFFFFull;   // sentinel
        }
    } else {
        // ------- softplus: flat coalesced grid-stride over cls region -------
        const float4* f40 = (const float4*)(p0 + ((size_t)b * 144 + 64) * N0);
        const float4* f41 = (const float4*)(p1 + ((size_t)b * 144 + 64) * N1);
        const float4* f42 = (const float4*)(p2 + ((size_t)b * 144 + 64) * N2);
        int blk = blockIdx.x - DEC_BLK;
        float acc = 0.f;
        float P0 = 1.f, P1 = 1.f, P2 = 1.f, P3 = 1.f;
        int cnt = 0;
        for (int i = blk * 256 + tid; i < SP_TOT; i += SP_BLK * 256) {
            float4 v;
            if (i < S0)           v = f40[i];
            else if (i < S0 + S1) v = f41[i - S0];
            else                  v = f42[i - S0 - S1];
            float e0 = __expf(v.x), e1 = __expf(v.y), e2 = __expf(v.z), e3 = __expf(v.w);
            P0 = fmaf(P0, e0, P0);   // P *= (1+e)
            P1 = fmaf(P1, e1, P1);
            P2 = fmaf(P2, e2, P2);
            P3 = fmaf(P3, e3, P3);
            if ((++cnt & 7) == 0) {  // flush every 32 elems; factors <= 1+e^~7
                acc += __logf((P0 * P1) * (P2 * P3));
                P0 = P1 = P2 = P3 = 1.f;
            }
        }
        acc += __logf((P0 * P1) * (P2 * P3));

        __shared__ double sred[256];
        sred[tid] = (double)acc;
        __syncthreads();
        for (int s = 128; s > 0; s >>= 1) {
            if (tid < s) sred[tid] += sred[tid + s];
            __syncthreads();
        }
        if (tid == 0) g_sp_part[b * SP_BLK + blk] = sred[0];
    }
}

// ================= k_assign: one block per (b,m), rect scan + fg compaction =====
__global__ void __launch_bounds__(256) k_assign(
        const float* __restrict__ p0, const float* __restrict__ p1,
        const float* __restrict__ p2,
        const float* __restrict__ gt_boxes, const int* __restrict__ gt_labels,
        const float* __restrict__ strides) {
    __shared__ unsigned long long sh_keys[256 * TOPKK];
    __shared__ unsigned long long sh_w[8];
    __shared__ unsigned long long sh_best;
    __shared__ float sh_fw[8];
    __shared__ float sh_cmax;

    int b = blockIdx.x >> 5, m = blockIdx.x & 31;
    int tid = threadIdx.x;
    int wid = tid >> 5, lid = tid & 31;

    float gx1 = gt_boxes[(b * MM + m) * 4 + 0];
    float gy1 = gt_boxes[(b * MM + m) * 4 + 1];
    float gx2 = gt_boxes[(b * MM + m) * 4 + 2];
    float gy2 = gt_boxes[(b * MM + m) * 4 + 3];
    int label = gt_labels[b * MM + m];

    float tv[TOPKK]; int tn[TOPKK];
#pragma unroll
    for (int jj = 0; jj < TOPKK; jj++) { tv[jj] = 0.f; tn[jj] = 0x7FFFFFFF; }
    float cmax = 0.f;

#pragma unroll
    for (int lvl = 0; lvl < 3; lvl++) {
        const float* p; int HW, W, noff; float st;
        if (lvl == 0)      { p = p0; HW = N0; W = 160; noff = 0;       st = strides[0]; }
        else if (lvl == 1) { p = p1; HW = N1; W = 80;  noff = N0;      st = strides[1]; }
        else               { p = p2; HW = N2; W = 40;  noff = N0 + N1; st = strides[2]; }

        float inv = 1.f / st;
        int x0 = max(0, (int)(gx1 * inv - 0.5f) - 1);
        int x1 = min(W - 1, (int)(gx2 * inv - 0.5f) + 1);
        int y0 = max(0, (int)(gy1 * inv - 0.5f) - 1);
        int y1 = min(W - 1, (int)(gy2 * inv - 0.5f) + 1);
        int rw = x1 - x0 + 1, rh = y1 - y0 + 1;
        if (rw <= 0 || rh <= 0) continue;
        int tot = rw * rh;
        const float* pcl = p + ((size_t)b * 144 + 64 + label) * HW;

        for (int i = tid; i < tot; i += 256) {
            int qx = x0 + i % rw;
            int qy = y0 + i / rw;
            float ax = ((float)qx + 0.5f) * st;
            float ay = ((float)qy + 0.5f) * st;
            if (ax < gx1 || ax > gx2 || ay < gy1 || ay > gy2) continue;
            int q = qy * W + qx;
            int n = noff + q;
            float4 pbv = g_pb[b * NTOT + n];
            float iou = fmaxf(ciou_f(pbv.x, pbv.y, pbv.z, pbv.w, gx1, gy1, gx2, gy2), 0.f);
            float ps = 1.f / (1.f + __expf(-pcl[q]));
            float i2 = iou * iou;
            float align = ps * (i2 * i2 * i2);
            cmax = fmaxf(cmax, align);
            if (iou > 0.1f && align > 0.f &&
                ((align > tv[TOPKK - 1]) ||
                 (align == tv[TOPKK - 1] && n < tn[TOPKK - 1]))) {
                float cv = align; int cn = n;
#pragma unroll
                for (int jj = 0; jj < TOPKK; jj++) {
                    bool bt = (cv > tv[jj]) || (cv == tv[jj] && cn < tn[jj]);
                    float nv = bt ? cv : tv[jj];  int nn = bt ? cn : tn[jj];
                    cv = bt ? tv[jj] : cv;        cn = bt ? tn[jj] : cn;
                    tv[jj] = nv;                  tn[jj] = nn;
                }
            }
        }
    }

#pragma unroll
    for (int d = 16; d > 0; d >>= 1)
        cmax = fmaxf(cmax, __shfl_down_sync(0xffffffffu, cmax, d));
    if (lid == 0) sh_fw[wid] = cmax;
    __syncthreads();
    if (tid == 0) {
        float c = sh_fw[0];
#pragma unroll
        for (int w = 1; w < 8; w++) c = fmaxf(c, sh_fw[w]);
        sh_cmax = c;
    }

#pragma unroll
    for (int jj = 0; jj < TOPKK; jj++) {
        unsigned long long key = 0ull;
        if (tv[jj] > 0.f)
            key = ((unsigned long long)__float_as_uint(tv[jj]) << 32) |
                  (unsigned long long)(0xFFFFFFFFu - (unsigned)tn[jj]);
        sh_keys[tid * TOPKK + jj] = key;
    }
    __syncthreads();
    float colmax = sh_cmax;

    for (int iter = 0; iter < TOPKK; iter++) {
        unsigned long long loc = 0ull;
#pragma unroll
        for (int jj = 0; jj < TOPKK; jj++)
            loc = umax64(loc, sh_keys[tid + jj * 256]);
        loc = warp_max64(loc);
        if (lid == 0) sh_w[wid] = loc;
        __syncthreads();
        if (tid == 0) {
            unsigned long long v = sh_w[0];
#pragma unroll
            for (int w = 1; w < 8; w++) v = umax64(v, sh_w[w]);
            sh_best = v;
        }
        __syncthreads();
        unsigned long long bestk = sh_best;
        if (bestk == 0ull) break;
#pragma unroll
        for (int jj = 0; jj < TOPKK; jj++)
            if (sh_keys[tid * TOPKK + jj] == bestk) sh_keys[tid * TOPKK + jj] = 0ull;
        if (tid == 0) {
            float val = __uint_as_float((unsigned)(bestk >> 32));
            int n = (int)(0xFFFFFFFFu - (unsigned)(bestk & 0xFFFFFFFFull));
            float norm = val / (colmax + 1e-9f);
            unsigned long long okey =
                ((unsigned long long)__float_as_uint(norm) << 32) |
                (unsigned long long)(0xFFFFFFFFu - (unsigned)m);
            int gidx = b * NTOT + n;
            unsigned long long old = atomicMax(&g_best[gidx], okey);
            if (old == 0xFFFFFFFFull) {     // first writer -> compaction
                atomicAdd(&g_fgcnt[b], 1);
                int pos = atomicAdd(&g_fgtot, 1);
                g_fglist[pos] = gidx;
            }
        }
        __syncthreads();
    }
}

// ====== k_fg: thread-per-anchor (lse-based, 9 loads) + last-block final combine ======
__global__ void __launch_bounds__(128) k_fg(
        const float* __restrict__ p0, const float* __restrict__ p1,
        const float* __restrict__ p2,
        const float* __restrict__ gt_boxes, const int* __restrict__ gt_labels,
        const float* __restrict__ strides, float* __restrict__ out) {
    int tid = threadIdx.x;
    int i = blockIdx.x * 128 + tid;

    __shared__ float sbox[BB], sdfl[BB], scls[BB];
    if (tid < BB) { sbox[tid] = 0.f; sdfl[tid] = 0.f; scls[tid] = 0.f; }
    __syncthreads();

    if (i < g_fgtot) {
        int idx = g_fglist[i];
        unsigned long long key = g_best[idx];
        float score = __uint_as_float((unsigned)(key >> 32));
        int b = idx / NTOT, n = idx - (idx / NTOT) * NTOT;
        int m = (int)(0xFFFFFFFFu - (unsigned)(key & 0xFFFFFFFFull));

        float4 g = ((const float4*)gt_boxes)[b * MM + m];
        int label = gt_labels[b * MM + m];

        const float* p; int HW, W, q; float st;
        if (n < N0)           { p = p0; HW = N0; W = 160; q = n;             st = strides[0]; }
        else if (n < N0 + N1) { p = p1; HW = N1; W = 80;  q = n - N0;        st = strides[1]; }
        else                  { p = p2; HW = N2; W = 40;  q = n - (N0 + N1); st = strides[2]; }
        int qy = q / W;
        float ax = (float)(q - qy * W) + 0.5f;
        float ay = (float)qy + 0.5f;

        float4 pbv = g_pb[idx];
        float4 lse = g_lse[idx];
        float boxl = 1.f - ciou_f(pbv.x, pbv.y, pbv.z, pbv.w, g.x, g.y, g.z, g.w);

        float t0 = fminf(fmaxf(ax - g.x / st, 0.f), 14.99f);
        float t1 = fminf(fmaxf(ay - g.y / st, 0.f), 14.99f);
        float t2 = fminf(fmaxf(g.z / st - ax, 0.f), 14.99f);
        float t3 = fminf(fmaxf(g.w / st - ay, 0.f), 14.99f);
        int l0 = (int)t0, l1 = (int)t1, l2 = (int)t2, l3 = (int)t3;
        int r0 = min(l0 + 1, 15), r1 = min(l1 + 1, 15), r2 = min(l2 + 1, 15), r3 = min(l3 + 1, 15);

        const float* base = p + (size_t)b * 144 * HW + q;
        float xl0 = base[(size_t)l0 * HW];
        float xr0 = base[(size_t)r0 * HW];
        float xl1 = base[(size_t)(16 + l1) * HW];
        float xr1 = base[(size_t)(16 + r1) * HW];
        float xl2 = base[(size_t)(32 + l2) * HW];
        float xr2 = base[(size_t)(32 + r2) * HW];
        float xl3 = base[(size_t)(48 + l3) * HW];
        float xr3 = base[(size_t)(48 + r3) * HW];
        float pcv = base[(size_t)(64 + label) * HW];

        float dfl =
            ((float)r0 - t0) * (lse.x - xl0) + (t0 - (float)l0) * (lse.x - xr0) +
            ((float)r1 - t1) * (lse.y - xl1) + (t1 - (float)l1) * (lse.y - xr1) +
            ((float)r2 - t2) * (lse.z - xl2) + (t2 - (float)l2) * (lse.z - xr2) +
            ((float)r3 - t3) * (lse.w - xl3) + (t3 - (float)l3) * (lse.w - xr3);

        atomicAdd(&sbox[b], boxl);
        atomicAdd(&sdfl[b], dfl);
        atomicAdd(&scls[b], pcv * score);
    }
    __syncthreads();
    if (tid < BB) {
        if (sbox[tid] != 0.f) atomicAdd(&g_box[tid], sbox[tid]);
        if (sdfl[tid] != 0.f) atomicAdd(&g_dfl[tid], sdfl[tid]);
        if (scls[tid] != 0.f) atomicAdd(&g_clspos[tid], scls[tid]);
    }

    // ---- last block folds in the final combine ----
    __shared__ bool s_last;
    __syncthreads();
    if (tid == 0) {
        __threadfence();
        unsigned v = atomicAdd(&g_done, 1u);
        s_last = (v == (unsigned)(gridDim.x - 1));
    }
    __syncthreads();
    if (!s_last) return;

    int w = tid >> 5, l = tid & 31;
    __shared__ double s8[8];
    if (w < 4) {
        // 4 warps handle 8 images: warp w does images w and w+4
        for (int bb = w; bb < BB; bb += 4) {
            double sp = 0.0;
            for (int j = l; j < SP_BLK; j += 32) sp += g_sp_part[bb * SP_BLK + j];
#pragma unroll
            for (int d = 16; d > 0; d >>= 1) sp += __shfl_down_sync(0xffffffffu, sp, d);
            if (l == 0) {
                int cnt = g_fgcnt[bb];
                double has = cnt > 0 ? 1.0 : 0.0;
                double nf = cnt > 0 ? (double)cnt : 1.0;
                double bl = (double)g_box[bb] / nf;
                double dl = (double)g_dfl[bb] / (nf * 4.0);
                double cl = (sp - (double)g_clspos[bb]) / (double)NTOT;
                s8[bb] = (7.5 * bl + 0.5 * cl + 1.5 * dl) * has;
            }
        }
    }
    __syncthreads();
    if (tid == 0) {
        double total = 0.0;
#pragma unroll
        for (int b = 0; b < BB; b++) total += s8[b];
        out[0] = (float)total;
    }
}

// ---------------- launch: simple 3-node linear graph ----------------
extern "C" void kernel_launch(void* const* d_in, const int* in_sizes, int n_in,
                              void* d_out, int out_size) {
    const float* p0 = (const float*)d_in[0];
    const float* p1 = (const float*)d_in[1];
    const float* p2 = (const float*)d_in[2];
    const float* gtb = (const float*)d_in[3];
    const int* gtl = (const int*)d_in[4];
    const float* strides = (const float*)d_in[5];
    float* out = (float*)d_out;

    k_main<<<dim3(DEC_BLK + SP_BLK, BB), 256>>>(p0, p1, p2, gtb, strides);
    k_assign<<<BB * MM, 256>>>(p0, p1, p2, gtb, gtl, strides);
    k_fg<<<FG_BLK, 128>>>(p0, p1, p2, gtb, gtl, strides, out);
}

// round 13
// speedup vs baseline: 1.4532x; 1.4109x over previous
#include <cuda_runtime.h>
#include <cstdint>

#define BB 8
#define MM 32
#define NCLS 80
#define N0 25600
#define N1 6400
#define N2 1600
#define NTOT 33600
#define TOPKK 10
#define QTOT 8400            // NTOT/4 (float4 anchors per image)
#define DEC_BLK 33           // decode blocks per image
#define SP_BLK 128           // softplus blocks per image
#define S0 512000            // 80*25600/4 float4 per image (p0 cls)
#define S1 128000
#define SP_TOT 672000
#define FG_MAX 2560
#define NB2 256              // k_tail blocks = BB*MM (all co-resident)

// ---------------- scratch ----------------
__device__ float4 g_pb[BB * NTOT];                 // decoded pred boxes (image units)
__device__ unsigned long long g_best[BB * NTOT];   // (score<<32 | ~m)
__device__ double g_sp_part[BB * SP_BLK];          // softplus block partials
__device__ int g_fglist[FG_MAX];
__device__ int g_fgtot;
__device__ int g_fgcnt[BB];
__device__ float g_box[BB], g_dfl[BB], g_clspos[BB];
__device__ unsigned g_bar_count;                   // zero-init
__device__ unsigned g_bar_gen;                     // monotonic across replays

// ---------------- helpers ----------------
__device__ __forceinline__ float ciou_f(float b1x1, float b1y1, float b1x2, float b1y2,
                                        float b2x1, float b2y1, float b2x2, float b2y2) {
    const float eps = 1e-7f;
    float w1 = b1x2 - b1x1, h1 = b1y2 - b1y1;
    float w2 = b2x2 - b2x1, h2 = b2y2 - b2y1;
    float iw = fminf(b1x2, b2x2) - fmaxf(b1x1, b2x1);
    float ih = fminf(b1y2, b2y2) - fmaxf(b1y1, b2y1);
    float inter = fmaxf(iw, 0.f) * fmaxf(ih, 0.f);
    float uni = w1 * h1 + w2 * h2 - inter + eps;
    float iou = inter / uni;
    float cw = fmaxf(b1x2, b2x2) - fminf(b1x1, b2x1);
    float ch = fmaxf(b1y2, b2y2) - fminf(b1y1, b2y1);
    float c2 = cw * cw + ch * ch + eps;
    float dx = b2x1 + b2x2 - b1x1 - b1x2;
    float dy = b2y1 + b2y2 - b1y1 - b1y2;
    float rho2 = (dx * dx + dy * dy) * 0.25f;
    float dat = atanf(w2 / (h2 + eps)) - atanf(w1 / (h1 + eps));
    float v = 0.4052847345693511f * dat * dat;
    float alpha = v / (v - iou + (1.f + eps));
    return iou - (rho2 / c2 + v * alpha);
}

__device__ __forceinline__ unsigned long long umax64(unsigned long long a, unsigned long long b) {
    return a > b ? a : b;
}

__device__ __forceinline__ unsigned long long warp_max64(unsigned long long v) {
#pragma unroll
    for (int d = 16; d > 0; d >>= 1)
        v = umax64(v, __shfl_down_sync(0xffffffffu, v, d));
    return v;
}

// sense-reversal grid barrier (gen monotonic -> graph-replay-safe)
template <int NBLK>
__device__ __forceinline__ void gsync() {
    __syncthreads();
    if (threadIdx.x == 0) {
        __threadfence();
        unsigned gen = atomicAdd(&g_bar_gen, 0u);
        unsigned old = atomicAdd(&g_bar_count, 1u);
        if (old == NBLK - 1) {
            atomicExch(&g_bar_count, 0u);
            __threadfence();
            atomicAdd(&g_bar_gen, 1u);
        } else {
            while (atomicAdd(&g_bar_gen, 0u) == gen) __nanosleep(64);
        }
        __threadfence();
    }
    __syncthreads();
}

// ============ k_main: R3's fused dense decode + softplus (verbatim; 41.9us measured) ====
__global__ void __launch_bounds__(256) k_main(
        const float* __restrict__ p0, const float* __restrict__ p1,
        const float* __restrict__ p2, const float* __restrict__ strides) {
    int b = blockIdx.y;
    int tid = threadIdx.x;

    if (blockIdx.x == 0 && tid == 0) {
        g_fgcnt[b] = 0; g_box[b] = 0.f; g_dfl[b] = 0.f; g_clspos[b] = 0.f;
        if (b == 0) g_fgtot = 0;
    }

    if (blockIdx.x < DEC_BLK) {
        // ---------------- decode: 4 anchors per thread ----------------
        int j = blockIdx.x * 256 + tid;
        if (j >= QTOT) return;
        const float* p; int HW, W, q4, noff; float st;
        if (j < 6400)      { p = p0; HW = N0; W = 160; q4 = j;        noff = 0;       st = strides[0]; }
        else if (j < 8000) { p = p1; HW = N1; W = 80;  q4 = j - 6400; noff = N0;      st = strides[1]; }
        else               { p = p2; HW = N2; W = 40;  q4 = j - 8000; noff = N0 + N1; st = strides[2]; }
        int q = q4 * 4;
        float ay = (float)(q / W) + 0.5f;
        float ax = (float)(q % W) + 0.5f;

        const float* pb = p + (size_t)b * 144 * HW + q;
        float4 out[4];
#pragma unroll
        for (int k = 0; k < 4; k++) {
            float se0 = 0.f, se1 = 0.f, se2 = 0.f, se3 = 0.f;
            float sw0 = 0.f, sw1 = 0.f, sw2 = 0.f, sw3 = 0.f;
#pragma unroll
            for (int r = 0; r < 16; r++) {
                float4 v = *(const float4*)(pb + (size_t)(k * 16 + r) * HW);
                float e0 = __expf(v.x), e1 = __expf(v.y), e2 = __expf(v.z), e3 = __expf(v.w);
                float fr = (float)r;
                se0 += e0; sw0 = fmaf(e0, fr, sw0);
                se1 += e1; sw1 = fmaf(e1, fr, sw1);
                se2 += e2; sw2 = fmaf(e2, fr, sw2);
                se3 += e3; sw3 = fmaf(e3, fr, sw3);
            }
            float d0 = sw0 / se0, d1 = sw1 / se1, d2 = sw2 / se2, d3 = sw3 / se3;
            if (k == 0) { out[0].x = (ax - d0) * st;        out[1].x = (ax + 1.f - d1) * st;
                          out[2].x = (ax + 2.f - d2) * st;  out[3].x = (ax + 3.f - d3) * st; }
            if (k == 1) { out[0].y = (ay - d0) * st; out[1].y = (ay - d1) * st;
                          out[2].y = (ay - d2) * st; out[3].y = (ay - d3) * st; }
            if (k == 2) { out[0].z = (ax + d0) * st;        out[1].z = (ax + 1.f + d1) * st;
                          out[2].z = (ax + 2.f + d2) * st;  out[3].z = (ax + 3.f + d3) * st; }
            if (k == 3) { out[0].w = (ay + d0) * st; out[1].w = (ay + d1) * st;
                          out[2].w = (ay + d2) * st; out[3].w = (ay + d3) * st; }
        }
        int base = b * NTOT + noff + q;
#pragma unroll
        for (int a = 0; a < 4; a++) {
            g_pb[base + a] = out[a];
            g_best[base + a] = 0xFFFFFFFFull;   // sentinel: score 0, m = 0
        }
    } else {
        // ---------------- softplus: flat coalesced grid-stride ----------------
        const float4* f40 = (const float4*)(p0 + ((size_t)b * 144 + 64) * N0);
        const float4* f41 = (const float4*)(p1 + ((size_t)b * 144 + 64) * N1);
        const float4* f42 = (const float4*)(p2 + ((size_t)b * 144 + 64) * N2);
        int blk = blockIdx.x - DEC_BLK;
        float acc = 0.f;
        float P0 = 1.f, P1 = 1.f, P2 = 1.f, P3 = 1.f;
        int cnt = 0;
        for (int i = blk * 256 + tid; i < SP_TOT; i += SP_BLK * 256) {
            float4 v;
            if (i < S0)           v = f40[i];
            else if (i < S0 + S1) v = f41[i - S0];
            else                  v = f42[i - S0 - S1];
            acc += fmaxf(v.x, 0.f) + fmaxf(v.y, 0.f) + fmaxf(v.z, 0.f) + fmaxf(v.w, 0.f);
            P0 *= 1.f + __expf(-fabsf(v.x));
            P1 *= 1.f + __expf(-fabsf(v.y));
            P2 *= 1.f + __expf(-fabsf(v.z));
            P3 *= 1.f + __expf(-fabsf(v.w));
            if ((++cnt & 7) == 0) {   // flush every 32 terms (each <= 2)
                acc += __logf((P0 * P1) * (P2 * P3));
                P0 = P1 = P2 = P3 = 1.f;
            }
        }
        acc += __logf((P0 * P1) * (P2 * P3));

        __shared__ double sred[256];
        sred[tid] = (double)acc;
        __syncthreads();
        for (int s = 128; s > 0; s >>= 1) {
            if (tid < s) sred[tid] += sred[tid + s];
            __syncthreads();
        }
        if (tid == 0) g_sp_part[b * SP_BLK + blk] = sred[0];
    }
}

// ======= k_tail: assign -> grid barrier -> fg (warp/anchor) -> barrier -> final ========
__global__ void __launch_bounds__(256) k_tail(
        const float* __restrict__ p0, const float* __restrict__ p1,
        const float* __restrict__ p2,
        const float* __restrict__ gt_boxes, const int* __restrict__ gt_labels,
        const float* __restrict__ strides, float* __restrict__ out) {
    __shared__ unsigned long long sh_keys[256 * TOPKK];
    __shared__ unsigned long long sh_w[8];
    __shared__ unsigned long long sh_best;
    __shared__ float sh_fw[8];
    __shared__ float sh_cmax;

    int tid = threadIdx.x;
    int wid = tid >> 5, lid = tid & 31;

    // ---------------- phase A: assign (one block per (b,m)) ----------------
    {
        int b = blockIdx.x >> 5, m = blockIdx.x & 31;
        float gx1 = gt_boxes[(b * MM + m) * 4 + 0];
        float gy1 = gt_boxes[(b * MM + m) * 4 + 1];
        float gx2 = gt_boxes[(b * MM + m) * 4 + 2];
        float gy2 = gt_boxes[(b * MM + m) * 4 + 3];
        int label = gt_labels[b * MM + m];

        float tv[TOPKK]; int tn[TOPKK];
#pragma unroll
        for (int jj = 0; jj < TOPKK; jj++) { tv[jj] = 0.f; tn[jj] = 0x7FFFFFFF; }
        float cmax = 0.f;

#pragma unroll
        for (int lvl = 0; lvl < 3; lvl++) {
            const float* p; int HW, W, noff; float st;
            if (lvl == 0)      { p = p0; HW = N0; W = 160; noff = 0;       st = strides[0]; }
            else if (lvl == 1) { p = p1; HW = N1; W = 80;  noff = N0;      st = strides[1]; }
            else               { p = p2; HW = N2; W = 40;  noff = N0 + N1; st = strides[2]; }

            float inv = 1.f / st;
            int x0 = max(0, (int)(gx1 * inv - 0.5f) - 1);
            int x1 = min(W - 1, (int)(gx2 * inv - 0.5f) + 1);
            int y0 = max(0, (int)(gy1 * inv - 0.5f) - 1);
            int y1 = min(W - 1, (int)(gy2 * inv - 0.5f) + 1);
            int rw = x1 - x0 + 1, rh = y1 - y0 + 1;
            if (rw <= 0 || rh <= 0) continue;
            int tot = rw * rh;
            const float* pcl = p + ((size_t)b * 144 + 64 + label) * HW;

            for (int i = tid; i < tot; i += 256) {
                int qx = x0 + i % rw;
                int qy = y0 + i / rw;
                float ax = ((float)qx + 0.5f) * st;
                float ay = ((float)qy + 0.5f) * st;
                if (ax < gx1 || ax > gx2 || ay < gy1 || ay > gy2) continue;
                int q = qy * W + qx;
                int n = noff + q;
                float4 pbv = g_pb[b * NTOT + n];
                float iou = fmaxf(ciou_f(pbv.x, pbv.y, pbv.z, pbv.w, gx1, gy1, gx2, gy2), 0.f);
                float ps = 1.f / (1.f + __expf(-pcl[q]));
                float i2 = iou * iou;
                float align = ps * (i2 * i2 * i2);
                cmax = fmaxf(cmax, align);
                if (iou > 0.1f && align > 0.f &&
                    ((align > tv[TOPKK - 1]) ||
                     (align == tv[TOPKK - 1] && n < tn[TOPKK - 1]))) {
                    float cv = align; int cn = n;
#pragma unroll
                    for (int jj = 0; jj < TOPKK; jj++) {
                        bool bt = (cv > tv[jj]) || (cv == tv[jj] && cn < tn[jj]);
                        float nv = bt ? cv : tv[jj];  int nn = bt ? cn : tn[jj];
                        cv = bt ? tv[jj] : cv;        cn = bt ? tn[jj] : cn;
                        tv[jj] = nv;                  tn[jj] = nn;
                    }
                }
            }
        }

#pragma unroll
        for (int d = 16; d > 0; d >>= 1)
            cmax = fmaxf(cmax, __shfl_down_sync(0xffffffffu, cmax, d));
        if (lid == 0) sh_fw[wid] = cmax;
        __syncthreads();
        if (tid == 0) {
            float c = sh_fw[0];
#pragma unroll
            for (int w = 1; w < 8; w++) c = fmaxf(c, sh_fw[w]);
            sh_cmax = c;
        }
#pragma unroll
        for (int jj = 0; jj < TOPKK; jj++) {
            unsigned long long key = 0ull;
            if (tv[jj] > 0.f)
                key = ((unsigned long long)__float_as_uint(tv[jj]) << 32) |
                      (unsigned long long)(0xFFFFFFFFu - (unsigned)tn[jj]);
            sh_keys[tid * TOPKK + jj] = key;
        }
        __syncthreads();
        float colmax = sh_cmax;

        for (int iter = 0; iter < TOPKK; iter++) {
            unsigned long long loc = 0ull;
#pragma unroll
            for (int jj = 0; jj < TOPKK; jj++)
                loc = umax64(loc, sh_keys[tid + jj * 256]);
            loc = warp_max64(loc);
            if (lid == 0) sh_w[wid] = loc;
            __syncthreads();
            if (tid == 0) {
                unsigned long long v = sh_w[0];
#pragma unroll
                for (int w = 1; w < 8; w++) v = umax64(v, sh_w[w]);
                sh_best = v;
            }
            __syncthreads();
            unsigned long long bestk = sh_best;
            if (bestk == 0ull) break;
#pragma unroll
            for (int jj = 0; jj < TOPKK; jj++)
                if (sh_keys[tid * TOPKK + jj] == bestk) sh_keys[tid * TOPKK + jj] = 0ull;
            if (tid == 0) {
                float val = __uint_as_float((unsigned)(bestk >> 32));
                int n = (int)(0xFFFFFFFFu - (unsigned)(bestk & 0xFFFFFFFFull));
                float norm = val / (colmax + 1e-9f);
                unsigned long long okey =
                    ((unsigned long long)__float_as_uint(norm) << 32) |
                    (unsigned long long)(0xFFFFFFFFu - (unsigned)m);
                int gidx = b * NTOT + n;
                unsigned long long old = atomicMax(&g_best[gidx], okey);
                if (old == 0xFFFFFFFFull) {     // first writer -> compaction
                    atomicAdd(&g_fgcnt[b], 1);
                    int pos = atomicAdd(&g_fgtot, 1);
                    g_fglist[pos] = gidx;
                }
            }
            __syncthreads();
        }
    }
    gsync<NB2>();

    // ---------------- phase B: fg losses, one warp per fg anchor ----------------
    int fgtot = g_fgtot;
    for (int i = blockIdx.x * 8 + wid; i < fgtot; i += NB2 * 8) {
        int idx = g_fglist[i];
        unsigned long long key = g_best[idx];
        float score = __uint_as_float((unsigned)(key >> 32));
        int b = idx / NTOT, n = idx - (idx / NTOT) * NTOT;
        int m = (int)(0xFFFFFFFFu - (unsigned)(key & 0xFFFFFFFFull));

        float4 g = ((const float4*)gt_boxes)[b * MM + m];
        int label = gt_labels[b * MM + m];

        const float* p; int HW, W, q; float st;
        if (n < N0)           { p = p0; HW = N0; W = 160; q = n;             st = strides[0]; }
        else if (n < N0 + N1) { p = p1; HW = N1; W = 80;  q = n - N0;        st = strides[1]; }
        else                  { p = p2; HW = N2; W = 40;  q = n - (N0 + N1); st = strides[2]; }
        int qy = q / W;
        float ax = (float)(q - qy * W) + 0.5f;
        float ay = (float)qy + 0.5f;

        const float* base = p + (size_t)b * 144 * HW + q;
        float x0 = base[(size_t)lid * HW];          // channels 0-31  (sides 0,1)
        float x1 = base[(size_t)(lid + 32) * HW];   // channels 32-63 (sides 2,3)

        float e0 = __expf(x0), e1 = __expf(x1);
#pragma unroll
        for (int d = 1; d < 16; d <<= 1) {
            e0 += __shfl_xor_sync(0xffffffffu, e0, d);
            e1 += __shfl_xor_sync(0xffffffffu, e1, d);
        }
        float lse0 = __logf(__shfl_sync(0xffffffffu, e0, 0));
        float lse1 = __logf(__shfl_sync(0xffffffffu, e0, 16));
        float lse2 = __logf(__shfl_sync(0xffffffffu, e1, 0));
        float lse3 = __logf(__shfl_sync(0xffffffffu, e1, 16));

        float t0 = fminf(fmaxf(ax - g.x / st, 0.f), 14.99f);
        float t1 = fminf(fmaxf(ay - g.y / st, 0.f), 14.99f);
        float t2 = fminf(fmaxf(g.z / st - ax, 0.f), 14.99f);
        float t3 = fminf(fmaxf(g.w / st - ay, 0.f), 14.99f);
        int l0 = (int)t0, l1 = (int)t1, l2 = (int)t2, l3 = (int)t3;
        int r0 = min(l0 + 1, 15), r1 = min(l1 + 1, 15), r2 = min(l2 + 1, 15), r3 = min(l3 + 1, 15);

        float xl0 = __shfl_sync(0xffffffffu, x0, l0);
        float xr0 = __shfl_sync(0xffffffffu, x0, r0);
        float xl1 = __shfl_sync(0xffffffffu, x0, 16 + l1);
        float xr1 = __shfl_sync(0xffffffffu, x0, 16 + r1);
        float xl2 = __shfl_sync(0xffffffffu, x1, l2);
        float xr2 = __shfl_sync(0xffffffffu, x1, r2);
        float xl3 = __shfl_sync(0xffffffffu, x1, 16 + l3);
        float xr3 = __shfl_sync(0xffffffffu, x1, 16 + r3);

        if (lid == 0) {
            float dfl =
                ((float)r0 - t0) * (lse0 - xl0) + (t0 - (float)l0) * (lse0 - xr0) +
                ((float)r1 - t1) * (lse1 - xl1) + (t1 - (float)l1) * (lse1 - xr1) +
                ((float)r2 - t2) * (lse2 - xl2) + (t2 - (float)l2) * (lse2 - xr2) +
                ((float)r3 - t3) * (lse3 - xl3) + (t3 - (float)l3) * (lse3 - xr3);

            float4 pbv = g_pb[idx];
            float boxl = 1.f - ciou_f(pbv.x, pbv.y, pbv.z, pbv.w, g.x, g.y, g.z, g.w);
            float pcv = base[(size_t)(64 + label) * HW];

            atomicAdd(&g_box[b], boxl);
            atomicAdd(&g_dfl[b], dfl);
            atomicAdd(&g_clspos[b], pcv * score);
        }
    }
    gsync<NB2>();

    // ---------------- phase C: final combine (block 0) ----------------
    if (blockIdx.x == 0) {
        __shared__ double s8[8];
        if (wid < 8) {
            double sp = 0.0;
            for (int j = lid; j < SP_BLK; j += 32) sp += g_sp_part[wid * SP_BLK + j];
#pragma unroll
            for (int d = 16; d > 0; d >>= 1) sp += __shfl_down_sync(0xffffffffu, sp, d);
            if (lid == 0) {
                int cnt = g_fgcnt[wid];
                double has = cnt > 0 ? 1.0 : 0.0;
                double nf = cnt > 0 ? (double)cnt : 1.0;
                double bl = (double)g_box[wid] / nf;
                double dl = (double)g_dfl[wid] / (nf * 4.0);
                double cl = (sp - (double)g_clspos[wid]) / (double)NTOT;
                s8[wid] = (7.5 * bl + 0.5 * cl + 1.5 * dl) * has;
            }
        }
        __syncthreads();
        if (tid == 0) {
            double total = 0.0;
#pragma unroll
            for (int b = 0; b < BB; b++) total += s8[b];
            out[0] = (float)total;
        }
    }
}

// ---------------- launch: TWO kernels, no events ----------------
extern "C" void kernel_launch(void* const* d_in, const int* in_sizes, int n_in,
                              void* d_out, int out_size) {
    const float* p0 = (const float*)d_in[0];
    const float* p1 = (const float*)d_in[1];
    const float* p2 = (const float*)d_in[2];
    const float* gtb = (const float*)d_in[3];
    const int* gtl = (const int*)d_in[4];
    const float* strides = (const float*)d_in[5];
    float* out = (float*)d_out;

    k_main<<<dim3(DEC_BLK + SP_BLK, BB), 256>>>(p0, p1, p2, strides);
    k_tail<<<NB2, 256>>>(p0, p1, p2, gtb, gtl, strides, out);
}

// round 14
// speedup vs baseline: 1.5331x; 1.0550x over previous
#include <cuda_runtime.h>
#include <cstdint>

#define BB 8
#define MM 32
#define NCLS 80
#define N0 25600
#define N1 6400
#define N2 1600
#define NTOT 33600
#define TOPKK 10
#define QTOT 8400            // NTOT/4 (float4 anchors per image)
#define DEC_BLK 33           // decode blocks per image
#define SP_BLK 128           // softplus blocks per image
#define S0 512000            // 80*25600/4 float4 per image (p0 cls)
#define S1 128000
#define SP_TOT 672000
#define FG_MAX 2560
#define FG_BLK 320           // 2560 fg warps / 8 warps-per-block

// ---------------- scratch ----------------
__device__ float4 g_pb[BB * NTOT];                 // decoded pred boxes (image units)
__device__ unsigned long long g_best[BB * NTOT];   // (score<<32 | ~m)
__device__ double g_sp_part[BB * SP_BLK];          // softplus block partials
__device__ int g_fglist[FG_MAX];
__device__ int g_fgtot;
__device__ int g_fgcnt[BB];
__device__ float g_box[BB], g_dfl[BB], g_clspos[BB];
__device__ unsigned g_done;

// ---------------- helpers ----------------
__device__ __forceinline__ float ciou_f(float b1x1, float b1y1, float b1x2, float b1y2,
                                        float b2x1, float b2y1, float b2x2, float b2y2) {
    const float eps = 1e-7f;
    float w1 = b1x2 - b1x1, h1 = b1y2 - b1y1;
    float w2 = b2x2 - b2x1, h2 = b2y2 - b2y1;
    float iw = fminf(b1x2, b2x2) - fmaxf(b1x1, b2x1);
    float ih = fminf(b1y2, b2y2) - fmaxf(b1y1, b2y1);
    float inter = fmaxf(iw, 0.f) * fmaxf(ih, 0.f);
    float uni = w1 * h1 + w2 * h2 - inter + eps;
    float iou = inter / uni;
    float cw = fmaxf(b1x2, b2x2) - fminf(b1x1, b2x1);
    float ch = fmaxf(b1y2, b2y2) - fminf(b1y1, b2y1);
    float c2 = cw * cw + ch * ch + eps;
    float dx = b2x1 + b2x2 - b1x1 - b1x2;
    float dy = b2y1 + b2y2 - b1y1 - b1y2;
    float rho2 = (dx * dx + dy * dy) * 0.25f;
    float dat = atanf(w2 / (h2 + eps)) - atanf(w1 / (h1 + eps));
    float v = 0.4052847345693511f * dat * dat;
    float alpha = v / (v - iou + (1.f + eps));
    return iou - (rho2 / c2 + v * alpha);
}

__device__ __forceinline__ unsigned long long umax64(unsigned long long a, unsigned long long b) {
    return a > b ? a : b;
}

__device__ __forceinline__ unsigned long long warp_max64(unsigned long long v) {
#pragma unroll
    for (int d = 16; d > 0; d >>= 1)
        v = umax64(v, __shfl_down_sync(0xffffffffu, v, d));
    return v;
}

// ============ k_main: R3's fused dense decode + softplus (measured 41.9us) ============
__global__ void __launch_bounds__(256) k_main(
        const float* __restrict__ p0, const float* __restrict__ p1,
        const float* __restrict__ p2, const float* __restrict__ strides) {
    int b = blockIdx.y;
    int tid = threadIdx.x;

    if (blockIdx.x == 0 && tid == 0) {
        g_fgcnt[b] = 0; g_box[b] = 0.f; g_dfl[b] = 0.f; g_clspos[b] = 0.f;
        if (b == 0) { g_done = 0u; g_fgtot = 0; }
    }

    if (blockIdx.x < DEC_BLK) {
        // ---------------- decode: 4 anchors per thread ----------------
        int j = blockIdx.x * 256 + tid;
        if (j >= QTOT) return;
        const float* p; int HW, W, q4, noff; float st;
        if (j < 6400)      { p = p0; HW = N0; W = 160; q4 = j;        noff = 0;       st = strides[0]; }
        else if (j < 8000) { p = p1; HW = N1; W = 80;  q4 = j - 6400; noff = N0;      st = strides[1]; }
        else               { p = p2; HW = N2; W = 40;  q4 = j - 8000; noff = N0 + N1; st = strides[2]; }
        int q = q4 * 4;
        float ay = (float)(q / W) + 0.5f;
        float ax = (float)(q % W) + 0.5f;

        const float* pb = p + (size_t)b * 144 * HW + q;
        float4 out[4];
#pragma unroll
        for (int k = 0; k < 4; k++) {
            float se0 = 0.f, se1 = 0.f, se2 = 0.f, se3 = 0.f;
            float sw0 = 0.f, sw1 = 0.f, sw2 = 0.f, sw3 = 0.f;
#pragma unroll
            for (int r = 0; r < 16; r++) {
                float4 v = *(const float4*)(pb + (size_t)(k * 16 + r) * HW);
                float e0 = __expf(v.x), e1 = __expf(v.y), e2 = __expf(v.z), e3 = __expf(v.w);
                float fr = (float)r;
                se0 += e0; sw0 = fmaf(e0, fr, sw0);
                se1 += e1; sw1 = fmaf(e1, fr, sw1);
                se2 += e2; sw2 = fmaf(e2, fr, sw2);
                se3 += e3; sw3 = fmaf(e3, fr, sw3);
            }
            float d0 = sw0 / se0, d1 = sw1 / se1, d2 = sw2 / se2, d3 = sw3 / se3;
            if (k == 0) { out[0].x = (ax - d0) * st;        out[1].x = (ax + 1.f - d1) * st;
                          out[2].x = (ax + 2.f - d2) * st;  out[3].x = (ax + 3.f - d3) * st; }
            if (k == 1) { out[0].y = (ay - d0) * st; out[1].y = (ay - d1) * st;
                          out[2].y = (ay - d2) * st; out[3].y = (ay - d3) * st; }
            if (k == 2) { out[0].z = (ax + d0) * st;        out[1].z = (ax + 1.f + d1) * st;
                          out[2].z = (ax + 2.f + d2) * st;  out[3].z = (ax + 3.f + d3) * st; }
            if (k == 3) { out[0].w = (ay + d0) * st; out[1].w = (ay + d1) * st;
                          out[2].w = (ay + d2) * st; out[3].w = (ay + d3) * st; }
        }
        int base = b * NTOT + noff + q;
#pragma unroll
        for (int a = 0; a < 4; a++) {
            g_pb[base + a] = out[a];
            g_best[base + a] = 0xFFFFFFFFull;   // sentinel: score 0, m = 0
        }
    } else {
        // ---------------- softplus: flat coalesced grid-stride ----------------
        const float4* f40 = (const float4*)(p0 + ((size_t)b * 144 + 64) * N0);
        const float4* f41 = (const float4*)(p1 + ((size_t)b * 144 + 64) * N1);
        const float4* f42 = (const float4*)(p2 + ((size_t)b * 144 + 64) * N2);
        int blk = blockIdx.x - DEC_BLK;
        float acc = 0.f;
        float P0 = 1.f, P1 = 1.f, P2 = 1.f, P3 = 1.f;
        int cnt = 0;
        for (int i = blk * 256 + tid; i < SP_TOT; i += SP_BLK * 256) {
            float4 v;
            if (i < S0)           v = f40[i];
            else if (i < S0 + S1) v = f41[i - S0];
            else                  v = f42[i - S0 - S1];
            acc += fmaxf(v.x, 0.f) + fmaxf(v.y, 0.f) + fmaxf(v.z, 0.f) + fmaxf(v.w, 0.f);
            P0 *= 1.f + __expf(-fabsf(v.x));
            P1 *= 1.f + __expf(-fabsf(v.y));
            P2 *= 1.f + __expf(-fabsf(v.z));
            P3 *= 1.f + __expf(-fabsf(v.w));
            if ((++cnt & 7) == 0) {   // flush every 32 terms (each <= 2)
                acc += __logf((P0 * P1) * (P2 * P3));
                P0 = P1 = P2 = P3 = 1.f;
            }
        }
        acc += __logf((P0 * P1) * (P2 * P3));

        __shared__ double sred[256];
        sred[tid] = (double)acc;
        __syncthreads();
        for (int s = 128; s > 0; s >>= 1) {
            if (tid < s) sred[tid] += sred[tid + s];
            __syncthreads();
        }
        if (tid == 0) g_sp_part[b * SP_BLK + blk] = sred[0];
    }
}

// ================= k_assign: one block per (b,m), rect scan + fg compaction =====
__global__ void __launch_bounds__(256) k_assign(
        const float* __restrict__ p0, const float* __restrict__ p1,
        const float* __restrict__ p2,
        const float* __restrict__ gt_boxes, const int* __restrict__ gt_labels,
        const float* __restrict__ strides) {
    __shared__ unsigned long long sh_keys[256 * TOPKK];
    __shared__ unsigned long long sh_w[8];
    __shared__ unsigned long long sh_best;
    __shared__ float sh_fw[8];
    __shared__ float sh_cmax;

    int b = blockIdx.x >> 5, m = blockIdx.x & 31;
    int tid = threadIdx.x;
    int wid = tid >> 5, lid = tid & 31;

    float gx1 = gt_boxes[(b * MM + m) * 4 + 0];
    float gy1 = gt_boxes[(b * MM + m) * 4 + 1];
    float gx2 = gt_boxes[(b * MM + m) * 4 + 2];
    float gy2 = gt_boxes[(b * MM + m) * 4 + 3];
    int label = gt_labels[b * MM + m];

    float tv[TOPKK]; int tn[TOPKK];
#pragma unroll
    for (int jj = 0; jj < TOPKK; jj++) { tv[jj] = 0.f; tn[jj] = 0x7FFFFFFF; }
    float cmax = 0.f;

#pragma unroll
    for (int lvl = 0; lvl < 3; lvl++) {
        const float* p; int HW, W, noff; float st;
        if (lvl == 0)      { p = p0; HW = N0; W = 160; noff = 0;       st = strides[0]; }
        else if (lvl == 1) { p = p1; HW = N1; W = 80;  noff = N0;      st = strides[1]; }
        else               { p = p2; HW = N2; W = 40;  noff = N0 + N1; st = strides[2]; }

        float inv = 1.f / st;
        int x0 = max(0, (int)(gx1 * inv - 0.5f) - 1);
        int x1 = min(W - 1, (int)(gx2 * inv - 0.5f) + 1);
        int y0 = max(0, (int)(gy1 * inv - 0.5f) - 1);
        int y1 = min(W - 1, (int)(gy2 * inv - 0.5f) + 1);
        int rw = x1 - x0 + 1, rh = y1 - y0 + 1;
        if (rw <= 0 || rh <= 0) continue;
        int tot = rw * rh;
        const float* pcl = p + ((size_t)b * 144 + 64 + label) * HW;

        for (int i = tid; i < tot; i += 256) {
            int qx = x0 + i % rw;
            int qy = y0 + i / rw;
            float ax = ((float)qx + 0.5f) * st;
            float ay = ((float)qy + 0.5f) * st;
            if (ax < gx1 || ax > gx2 || ay < gy1 || ay > gy2) continue;
            int q = qy * W + qx;
            int n = noff + q;
            float4 pbv = g_pb[b * NTOT + n];
            float iou = fmaxf(ciou_f(pbv.x, pbv.y, pbv.z, pbv.w, gx1, gy1, gx2, gy2), 0.f);
            float ps = 1.f / (1.f + __expf(-pcl[q]));
            float i2 = iou * iou;
            float align = ps * (i2 * i2 * i2);
            cmax = fmaxf(cmax, align);
            if (iou > 0.1f && align > 0.f &&
                ((align > tv[TOPKK - 1]) ||
                 (align == tv[TOPKK - 1] && n < tn[TOPKK - 1]))) {
                float cv = align; int cn = n;
#pragma unroll
                for (int jj = 0; jj < TOPKK; jj++) {
                    bool bt = (cv > tv[jj]) || (cv == tv[jj] && cn < tn[jj]);
                    float nv = bt ? cv : tv[jj];  int nn = bt ? cn : tn[jj];
                    cv = bt ? tv[jj] : cv;        cn = bt ? tn[jj] : cn;
                    tv[jj] = nv;                  tn[jj] = nn;
                }
            }
        }
    }

#pragma unroll
    for (int d = 16; d > 0; d >>= 1)
        cmax = fmaxf(cmax, __shfl_down_sync(0xffffffffu, cmax, d));
    if (lid == 0) sh_fw[wid] = cmax;
    __syncthreads();
    if (tid == 0) {
        float c = sh_fw[0];
#pragma unroll
        for (int w = 1; w < 8; w++) c = fmaxf(c, sh_fw[w]);
        sh_cmax = c;
    }

#pragma unroll
    for (int jj = 0; jj < TOPKK; jj++) {
        unsigned long long key = 0ull;
        if (tv[jj] > 0.f)
            key = ((unsigned long long)__float_as_uint(tv[jj]) << 32) |
                  (unsigned long long)(0xFFFFFFFFu - (unsigned)tn[jj]);
        sh_keys[tid * TOPKK + jj] = key;
    }
    __syncthreads();
    float colmax = sh_cmax;

    for (int iter = 0; iter < TOPKK; iter++) {
        unsigned long long loc = 0ull;
#pragma unroll
        for (int jj = 0; jj < TOPKK; jj++)
            loc = umax64(loc, sh_keys[tid + jj * 256]);
        loc = warp_max64(loc);
        if (lid == 0) sh_w[wid] = loc;
        __syncthreads();
        if (tid == 0) {
            unsigned long long v = sh_w[0];
#pragma unroll
            for (int w = 1; w < 8; w++) v = umax64(v, sh_w[w]);
            sh_best = v;
        }
        __syncthreads();
        unsigned long long bestk = sh_best;
        if (bestk == 0ull) break;
#pragma unroll
        for (int jj = 0; jj < TOPKK; jj++)
            if (sh_keys[tid * TOPKK + jj] == bestk) sh_keys[tid * TOPKK + jj] = 0ull;
        if (tid == 0) {
            float val = __uint_as_float((unsigned)(bestk >> 32));
            int n = (int)(0xFFFFFFFFu - (unsigned)(bestk & 0xFFFFFFFFull));
            float norm = val / (colmax + 1e-9f);
            unsigned long long okey =
                ((unsigned long long)__float_as_uint(norm) << 32) |
                (unsigned long long)(0xFFFFFFFFu - (unsigned)m);
            int gidx = b * NTOT + n;
            unsigned long long old = atomicMax(&g_best[gidx], okey);
            if (old == 0xFFFFFFFFull) {     // first writer -> compaction for free
                atomicAdd(&g_fgcnt[b], 1);
                int pos = atomicAdd(&g_fgtot, 1);
                g_fglist[pos] = gidx;
            }
        }
        __syncthreads();
    }
}

// ===== k_fg: one warp per fg anchor (lane-parallel DFL) + last-block final combine =====
__global__ void __launch_bounds__(256) k_fg(
        const float* __restrict__ p0, const float* __restrict__ p1,
        const float* __restrict__ p2,
        const float* __restrict__ gt_boxes, const int* __restrict__ gt_labels,
        const float* __restrict__ strides, float* __restrict__ out) {
    int tid = threadIdx.x;
    int lane = tid & 31;
    int i = blockIdx.x * 8 + (tid >> 5);

    if (i < g_fgtot) {
        int idx = g_fglist[i];
        unsigned long long key = g_best[idx];
        float score = __uint_as_float((unsigned)(key >> 32));
        int b = idx / NTOT, n = idx - (idx / NTOT) * NTOT;
        int m = (int)(0xFFFFFFFFu - (unsigned)(key & 0xFFFFFFFFull));

        float4 g = ((const float4*)gt_boxes)[b * MM + m];
        int label = gt_labels[b * MM + m];

        const float* p; int HW, W, q; float st;
        if (n < N0)           { p = p0; HW = N0; W = 160; q = n;             st = strides[0]; }
        else if (n < N0 + N1) { p = p1; HW = N1; W = 80;  q = n - N0;        st = strides[1]; }
        else                  { p = p2; HW = N2; W = 40;  q = n - (N0 + N1); st = strides[2]; }
        int qy = q / W;
        float ax = (float)(q - qy * W) + 0.5f;
        float ay = (float)qy + 0.5f;

        const float* base = p + (size_t)b * 144 * HW + q;
        float x0 = base[(size_t)lane * HW];          // channels 0-31  (sides 0,1)
        float x1 = base[(size_t)(lane + 32) * HW];   // channels 32-63 (sides 2,3)

        float e0 = __expf(x0), e1 = __expf(x1);
#pragma unroll
        for (int d = 1; d < 16; d <<= 1) {
            e0 += __shfl_xor_sync(0xffffffffu, e0, d);
            e1 += __shfl_xor_sync(0xffffffffu, e1, d);
        }
        float lse0 = __logf(__shfl_sync(0xffffffffu, e0, 0));
        float lse1 = __logf(__shfl_sync(0xffffffffu, e0, 16));
        float lse2 = __logf(__shfl_sync(0xffffffffu, e1, 0));
        float lse3 = __logf(__shfl_sync(0xffffffffu, e1, 16));

        float t0 = fminf(fmaxf(ax - g.x / st, 0.f), 14.99f);
        float t1 = fminf(fmaxf(ay - g.y / st, 0.f), 14.99f);
        float t2 = fminf(fmaxf(g.z / st - ax, 0.f), 14.99f);
        float t3 = fminf(fmaxf(g.w / st - ay, 0.f), 14.99f);
        int l0 = (int)t0, l1 = (int)t1, l2 = (int)t2, l3 = (int)t3;
        int r0 = min(l0 + 1, 15), r1 = min(l1 + 1, 15), r2 = min(l2 + 1, 15), r3 = min(l3 + 1, 15);

        float xl0 = __shfl_sync(0xffffffffu, x0, l0);
        float xr0 = __shfl_sync(0xffffffffu, x0, r0);
        float xl1 = __shfl_sync(0xffffffffu, x0, 16 + l1);
        float xr1 = __shfl_sync(0xffffffffu, x0, 16 + r1);
        float xl2 = __shfl_sync(0xffffffffu, x1, l2);
        float xr2 = __shfl_sync(0xffffffffu, x1, r2);
        float xl3 = __shfl_sync(0xffffffffu, x1, 16 + l3);
        float xr3 = __shfl_sync(0xffffffffu, x1, 16 + r3);

        if (lane == 0) {
            float dfl =
                ((float)r0 - t0) * (lse0 - xl0) + (t0 - (float)l0) * (lse0 - xr0) +
                ((float)r1 - t1) * (lse1 - xl1) + (t1 - (float)l1) * (lse1 - xr1) +
                ((float)r2 - t2) * (lse2 - xl2) + (t2 - (float)l2) * (lse2 - xr2) +
                ((float)r3 - t3) * (lse3 - xl3) + (t3 - (float)l3) * (lse3 - xr3);

            float4 pbv = g_pb[idx];
            float boxl = 1.f - ciou_f(pbv.x, pbv.y, pbv.z, pbv.w, g.x, g.y, g.z, g.w);
            float pcv = base[(size_t)(64 + label) * HW];

            atomicAdd(&g_box[b], boxl);
            atomicAdd(&g_dfl[b], dfl);
            atomicAdd(&g_clspos[b], pcv * score);
        }
    }

    // ---- completion detection: last block computes the final scalar ----
    __shared__ bool s_last;
    __syncthreads();
    if (tid == 0) {
        __threadfence();
        unsigned v = atomicAdd(&g_done, 1u);
        s_last = (v == (unsigned)(gridDim.x - 1));
    }
    __syncthreads();
    if (!s_last) return;

    int w = tid >> 5, l = tid & 31;
    __shared__ double s8[8];
    if (w < 8) {
        double sp = 0.0;
        for (int j = l; j < SP_BLK; j += 32) sp += g_sp_part[w * SP_BLK + j];
#pragma unroll
        for (int d = 16; d > 0; d >>= 1) sp += __shfl_down_sync(0xffffffffu, sp, d);
        if (l == 0) {
            int cnt = g_fgcnt[w];
            double has = cnt > 0 ? 1.0 : 0.0;
            double nf = cnt > 0 ? (double)cnt : 1.0;
            double bl = (double)g_box[w] / nf;
            double dl = (double)g_dfl[w] / (nf * 4.0);
            double cl = (sp - (double)g_clspos[w]) / (double)NTOT;
            s8[w] = (7.5 * bl + 0.5 * cl + 1.5 * dl) * has;
        }
    }
    __syncthreads();
    if (tid == 0) {
        double total = 0.0;
#pragma unroll
        for (int b = 0; b < BB; b++) total += s8[b];
        out[0] = (float)total;
    }
}

// ---------------- launch: 3-node linear graph ----------------
extern "C" void kernel_launch(void* const* d_in, const int* in_sizes, int n_in,
                              void* d_out, int out_size) {
    const float* p0 = (const float*)d_in[0];
    const float* p1 = (const float*)d_in[1];
    const float* p2 = (const float*)d_in[2];
    const float* gtb = (const float*)d_in[3];
    const int* gtl = (const int*)d_in[4];
    const float* strides = (const float*)d_in[5];
    float* out = (float*)d_out;

    k_main<<<dim3(DEC_BLK + SP_BLK, BB), 256>>>(p0, p1, p2, strides);
    k_assign<<<BB * MM, 256>>>(p0, p1, p2, gtb, gtl, strides);
    k_fg<<<FG_BLK, 256>>>(p0, p1, p2, gtb, gtl, strides, out);
}

// round 15
// speedup vs baseline: 1.5554x; 1.0146x over previous
#include <cuda_runtime.h>
#include <cstdint>

#define BB 8
#define MM 32
#define NCLS 80
#define N0 25600
#define N1 6400
#define N2 1600
#define NTOT 33600
#define TOPKK 10
#define QTOT 8400            // NTOT/4 (float4 anchors per image)
#define DEC_BLK 33           // decode blocks per image
#define SP_BLK 128           // softplus blocks per image
#define S0 512000            // 80*25600/4 float4 per image (p0 cls)
#define S1 128000
#define SP_TOT 672000
#define FG_MAX 2560
#define FG_BLK 320           // 2560 fg warps / 8 warps-per-block

// ---------------- scratch ----------------
__device__ float4 g_pb[BB * NTOT];                 // decoded pred boxes (image units)
__device__ unsigned long long g_best[BB * NTOT];   // (score<<32 | ~m)
__device__ double g_sp_part[BB * SP_BLK];          // softplus block partials
__device__ int g_fglist[FG_MAX];
__device__ int g_fgtot;
__device__ int g_fgcnt[BB];
__device__ float g_box[BB], g_dfl[BB], g_clspos[BB];

// ---------------- helpers ----------------
__device__ __forceinline__ float ciou_f(float b1x1, float b1y1, float b1x2, float b1y2,
                                        float b2x1, float b2y1, float b2x2, float b2y2) {
    const float eps = 1e-7f;
    float w1 = b1x2 - b1x1, h1 = b1y2 - b1y1;
    float w2 = b2x2 - b2x1, h2 = b2y2 - b2y1;
    float iw = fminf(b1x2, b2x2) - fmaxf(b1x1, b2x1);
    float ih = fminf(b1y2, b2y2) - fmaxf(b1y1, b2y1);
    float inter = fmaxf(iw, 0.f) * fmaxf(ih, 0.f);
    float uni = w1 * h1 + w2 * h2 - inter + eps;
    float iou = inter / uni;
    float cw = fmaxf(b1x2, b2x2) - fminf(b1x1, b2x1);
    float ch = fmaxf(b1y2, b2y2) - fminf(b1y1, b2y1);
    float c2 = cw * cw + ch * ch + eps;
    float dx = b2x1 + b2x2 - b1x1 - b1x2;
    float dy = b2y1 + b2y2 - b1y1 - b1y2;
    float rho2 = (dx * dx + dy * dy) * 0.25f;
    float dat = atanf(w2 / (h2 + eps)) - atanf(w1 / (h1 + eps));
    float v = 0.4052847345693511f * dat * dat;
    float alpha = v / (v - iou + (1.f + eps));
    return iou - (rho2 / c2 + v * alpha);
}

__device__ __forceinline__ unsigned long long umax64(unsigned long long a, unsigned long long b) {
    return a > b ? a : b;
}

__device__ __forceinline__ unsigned long long warp_max64(unsigned long long v) {
#pragma unroll
    for (int d = 16; d > 0; d >>= 1)
        v = umax64(v, __shfl_down_sync(0xffffffffu, v, d));
    return v;
}

// ============ k_decode: 4 anchors per thread, float4 channel loads (R3 decode half) =====
__global__ void __launch_bounds__(256) k_decode(
        const float* __restrict__ p0, const float* __restrict__ p1,
        const float* __restrict__ p2, const float* __restrict__ strides) {
    int b = blockIdx.y;
    int tid = threadIdx.x;

    if (blockIdx.x == 0 && tid == 0) {
        g_fgcnt[b] = 0; g_box[b] = 0.f; g_dfl[b] = 0.f; g_clspos[b] = 0.f;
        if (b == 0) g_fgtot = 0;
    }

    int j = blockIdx.x * 256 + tid;
    if (j >= QTOT) return;
    const float* p; int HW, W, q4, noff; float st;
    if (j < 6400)      { p = p0; HW = N0; W = 160; q4 = j;        noff = 0;       st = strides[0]; }
    else if (j < 8000) { p = p1; HW = N1; W = 80;  q4 = j - 6400; noff = N0;      st = strides[1]; }
    else               { p = p2; HW = N2; W = 40;  q4 = j - 8000; noff = N0 + N1; st = strides[2]; }
    int q = q4 * 4;
    float ay = (float)(q / W) + 0.5f;
    float ax = (float)(q % W) + 0.5f;

    const float* pb = p + (size_t)b * 144 * HW + q;
    float4 out[4];
#pragma unroll
    for (int k = 0; k < 4; k++) {
        float se0 = 0.f, se1 = 0.f, se2 = 0.f, se3 = 0.f;
        float sw0 = 0.f, sw1 = 0.f, sw2 = 0.f, sw3 = 0.f;
#pragma unroll
        for (int r = 0; r < 16; r++) {
            float4 v = *(const float4*)(pb + (size_t)(k * 16 + r) * HW);
            float e0 = __expf(v.x), e1 = __expf(v.y), e2 = __expf(v.z), e3 = __expf(v.w);
            float fr = (float)r;
            se0 += e0; sw0 = fmaf(e0, fr, sw0);
            se1 += e1; sw1 = fmaf(e1, fr, sw1);
            se2 += e2; sw2 = fmaf(e2, fr, sw2);
            se3 += e3; sw3 = fmaf(e3, fr, sw3);
        }
        float d0 = sw0 / se0, d1 = sw1 / se1, d2 = sw2 / se2, d3 = sw3 / se3;
        if (k == 0) { out[0].x = (ax - d0) * st;        out[1].x = (ax + 1.f - d1) * st;
                      out[2].x = (ax + 2.f - d2) * st;  out[3].x = (ax + 3.f - d3) * st; }
        if (k == 1) { out[0].y = (ay - d0) * st; out[1].y = (ay - d1) * st;
                      out[2].y = (ay - d2) * st; out[3].y = (ay - d3) * st; }
        if (k == 2) { out[0].z = (ax + d0) * st;        out[1].z = (ax + 1.f + d1) * st;
                      out[2].z = (ax + 2.f + d2) * st;  out[3].z = (ax + 3.f + d3) * st; }
        if (k == 3) { out[0].w = (ay + d0) * st; out[1].w = (ay + d1) * st;
                      out[2].w = (ay + d2) * st; out[3].w = (ay + d3) * st; }
    }
    int base = b * NTOT + noff + q;
#pragma unroll
    for (int a = 0; a < 4; a++) {
        g_pb[base + a] = out[a];
        g_best[base + a] = 0xFFFFFFFFull;   // sentinel: score 0, m = 0
    }
}

// ===== k_softplus: side branch; unrolled x3 for MLP (3 independent loads in flight) =====
__global__ void __launch_bounds__(256) k_softplus(
        const float* __restrict__ p0, const float* __restrict__ p1,
        const float* __restrict__ p2) {
    int b = blockIdx.y;
    int tid = threadIdx.x;
    const float4* f40 = (const float4*)(p0 + ((size_t)b * 144 + 64) * N0);
    const float4* f41 = (const float4*)(p1 + ((size_t)b * 144 + 64) * N1);
    const float4* f42 = (const float4*)(p2 + ((size_t)b * 144 + 64) * N2);

    const int STRIDE = SP_BLK * 256;     // 32768
    int i0 = blockIdx.x * 256 + tid;
    float acc = 0.f;
    float PA = 1.f, PB = 1.f, PC = 1.f, PD = 1.f;
    int cnt = 0;

    // SP_TOT = 672000 = 20 full strides + remainder 16640; unroll 3 strides at a time
    int i = i0;
    for (int blk3 = 0; blk3 < 6; blk3++) {          // 18 strides
        float4 va, vb, vc;
        int ia = i, ib = i + STRIDE, ic = i + 2 * STRIDE;
        va = (ia < S0) ? f40[ia] : (ia < S0 + S1 ? f41[ia - S0] : f42[ia - S0 - S1]);
        vb = (ib < S0) ? f40[ib] : (ib < S0 + S1 ? f41[ib - S0] : f42[ib - S0 - S1]);
        vc = (ic < S0) ? f40[ic] : (ic < S0 + S1 ? f42 == nullptr ? vb : f41[ic - S0] : f42[ic - S0 - S1]);
        // (the ternary chain above for vc is identical in structure; nullptr branch never taken)
        float ex;
        ex = __expf(va.x); PA = fmaf(PA, ex, PA);
        ex = __expf(va.y); PB = fmaf(PB, ex, PB);
        ex = __expf(va.z); PC = fmaf(PC, ex, PC);
        ex = __expf(va.w); PD = fmaf(PD, ex, PD);
        ex = __expf(vb.x); PA = fmaf(PA, ex, PA);
        ex = __expf(vb.y); PB = fmaf(PB, ex, PB);
        ex = __expf(vb.z); PC = fmaf(PC, ex, PC);
        ex = __expf(vb.w); PD = fmaf(PD, ex, PD);
        ex = __expf(vc.x); PA = fmaf(PA, ex, PA);
        ex = __expf(vc.y); PB = fmaf(PB, ex, PB);
        ex = __expf(vc.z); PC = fmaf(PC, ex, PC);
        ex = __expf(vc.w); PD = fmaf(PD, ex, PD);
        // flushed every 3 iters = 36 elements; factors <= 1+e^~7 -> (1100)^9 < 2^99, safe
        acc += __logf((PA * PB) * (PC * PD));
        PA = PB = PC = PD = 1.f;
        i += 3 * STRIDE;
        (void)cnt;
    }
    // remaining strides (indices 18*STRIDE .. SP_TOT)
    for (; i < SP_TOT; i += STRIDE) {
        float4 v;
        if (i < S0)           v = f40[i];
        else if (i < S0 + S1) v = f41[i - S0];
        else                  v = f42[i - S0 - S1];
        float ex;
        ex = __expf(v.x); PA = fmaf(PA, ex, PA);
        ex = __expf(v.y); PB = fmaf(PB, ex, PB);
        ex = __expf(v.z); PC = fmaf(PC, ex, PC);
        ex = __expf(v.w); PD = fmaf(PD, ex, PD);
    }
    acc += __logf((PA * PB) * (PC * PD));

    __shared__ double sred[256];
    sred[tid] = (double)acc;
    __syncthreads();
    for (int s = 128; s > 0; s >>= 1) {
        if (tid < s) sred[tid] += sred[tid + s];
        __syncthreads();
    }
    if (tid == 0) g_sp_part[b * SP_BLK + blockIdx.x] = sred[0];
}

// ================= k_assign: one block per (b,m), rect scan + fg compaction =====
__global__ void __launch_bounds__(256) k_assign(
        const float* __restrict__ p0, const float* __restrict__ p1,
        const float* __restrict__ p2,
        const float* __restrict__ gt_boxes, const int* __restrict__ gt_labels,
        const float* __restrict__ strides) {
    __shared__ unsigned long long sh_keys[256 * TOPKK];
    __shared__ unsigned long long sh_w[8];
    __shared__ unsigned long long sh_best;
    __shared__ float sh_fw[8];
    __shared__ float sh_cmax;

    int b = blockIdx.x >> 5, m = blockIdx.x & 31;
    int tid = threadIdx.x;
    int wid = tid >> 5, lid = tid & 31;

    float gx1 = gt_boxes[(b * MM + m) * 4 + 0];
    float gy1 = gt_boxes[(b * MM + m) * 4 + 1];
    float gx2 = gt_boxes[(b * MM + m) * 4 + 2];
    float gy2 = gt_boxes[(b * MM + m) * 4 + 3];
    int label = gt_labels[b * MM + m];

    float tv[TOPKK]; int tn[TOPKK];
#pragma unroll
    for (int jj = 0; jj < TOPKK; jj++) { tv[jj] = 0.f; tn[jj] = 0x7FFFFFFF; }
    float cmax = 0.f;

#pragma unroll
    for (int lvl = 0; lvl < 3; lvl++) {
        const float* p; int HW, W, noff; float st;
        if (lvl == 0)      { p = p0; HW = N0; W = 160; noff = 0;       st = strides[0]; }
        else if (lvl == 1) { p = p1; HW = N1; W = 80;  noff = N0;      st = strides[1]; }
        else               { p = p2; HW = N2; W = 40;  noff = N0 + N1; st = strides[2]; }

        float inv = 1.f / st;
        int x0 = max(0, (int)(gx1 * inv - 0.5f) - 1);
        int x1 = min(W - 1, (int)(gx2 * inv - 0.5f) + 1);
        int y0 = max(0, (int)(gy1 * inv - 0.5f) - 1);
        int y1 = min(W - 1, (int)(gy2 * inv - 0.5f) + 1);
        int rw = x1 - x0 + 1, rh = y1 - y0 + 1;
        if (rw <= 0 || rh <= 0) continue;
        int tot = rw * rh;
        const float* pcl = p + ((size_t)b * 144 + 64 + label) * HW;

        for (int i = tid; i < tot; i += 256) {
            int qx = x0 + i % rw;
            int qy = y0 + i / rw;
            float ax = ((float)qx + 0.5f) * st;
            float ay = ((float)qy + 0.5f) * st;
            if (ax < gx1 || ax > gx2 || ay < gy1 || ay > gy2) continue;
            int q = qy * W + qx;
            int n = noff + q;
            float4 pbv = g_pb[b * NTOT + n];
            float iou = fmaxf(ciou_f(pbv.x, pbv.y, pbv.z, pbv.w, gx1, gy1, gx2, gy2), 0.f);
            float ps = 1.f / (1.f + __expf(-pcl[q]));
            float i2 = iou * iou;
            float align = ps * (i2 * i2 * i2);
            cmax = fmaxf(cmax, align);
            if (iou > 0.1f && align > 0.f &&
                ((align > tv[TOPKK - 1]) ||
                 (align == tv[TOPKK - 1] && n < tn[TOPKK - 1]))) {
                float cv = align; int cn = n;
#pragma unroll
                for (int jj = 0; jj < TOPKK; jj++) {
                    bool bt = (cv > tv[jj]) || (cv == tv[jj] && cn < tn[jj]);
                    float nv = bt ? cv : tv[jj];  int nn = bt ? cn : tn[jj];
                    cv = bt ? tv[jj] : cv;        cn = bt ? tn[jj] : cn;
                    tv[jj] = nv;                  tn[jj] = nn;
                }
            }
        }
    }

#pragma unroll
    for (int d = 16; d > 0; d >>= 1)
        cmax = fmaxf(cmax, __shfl_down_sync(0xffffffffu, cmax, d));
    if (lid == 0) sh_fw[wid] = cmax;
    __syncthreads();
    if (tid == 0) {
        float c = sh_fw[0];
#pragma unroll
        for (int w = 1; w < 8; w++) c = fmaxf(c, sh_fw[w]);
        sh_cmax = c;
    }

#pragma unroll
    for (int jj = 0; jj < TOPKK; jj++) {
        unsigned long long key = 0ull;
        if (tv[jj] > 0.f)
            key = ((unsigned long long)__float_as_uint(tv[jj]) << 32) |
                  (unsigned long long)(0xFFFFFFFFu - (unsigned)tn[jj]);
        sh_keys[tid * TOPKK + jj] = key;
    }
    __syncthreads();
    float colmax = sh_cmax;

    for (int iter = 0; iter < TOPKK; iter++) {
        unsigned long long loc = 0ull;
#pragma unroll
        for (int jj = 0; jj < TOPKK; jj++)
            loc = umax64(loc, sh_keys[tid + jj * 256]);
        loc = warp_max64(loc);
        if (lid == 0) sh_w[wid] = loc;
        __syncthreads();
        if (tid == 0) {
            unsigned long long v = sh_w[0];
#pragma unroll
            for (int w = 1; w < 8; w++) v = umax64(v, sh_w[w]);
            sh_best = v;
        }
        __syncthreads();
        unsigned long long bestk = sh_best;
        if (bestk == 0ull) break;
#pragma unroll
        for (int jj = 0; jj < TOPKK; jj++)
            if (sh_keys[tid * TOPKK + jj] == bestk) sh_keys[tid * TOPKK + jj] = 0ull;
        if (tid == 0) {
            float val = __uint_as_float((unsigned)(bestk >> 32));
            int n = (int)(0xFFFFFFFFu - (unsigned)(bestk & 0xFFFFFFFFull));
            float norm = val / (colmax + 1e-9f);
            unsigned long long okey =
                ((unsigned long long)__float_as_uint(norm) << 32) |
                (unsigned long long)(0xFFFFFFFFu - (unsigned)m);
            int gidx = b * NTOT + n;
            unsigned long long old = atomicMax(&g_best[gidx], okey);
            if (old == 0xFFFFFFFFull) {     // first writer -> compaction for free
                atomicAdd(&g_fgcnt[b], 1);
                int pos = atomicAdd(&g_fgtot, 1);
                g_fglist[pos] = gidx;
            }
        }
        __syncthreads();
    }
}

// ===== k_fg: one warp per fg anchor (lane-parallel DFL); runs BEFORE the join =====
__global__ void __launch_bounds__(256) k_fg(
        const float* __restrict__ p0, const float* __restrict__ p1,
        const float* __restrict__ p2,
        const float* __restrict__ gt_boxes, const int* __restrict__ gt_labels,
        const float* __restrict__ strides) {
    int tid = threadIdx.x;
    int lane = tid & 31;
    int i = blockIdx.x * 8 + (tid >> 5);
    if (i >= g_fgtot) return;

    int idx = g_fglist[i];
    unsigned long long key = g_best[idx];
    float score = __uint_as_float((unsigned)(key >> 32));
    int b = idx / NTOT, n = idx - (idx / NTOT) * NTOT;
    int m = (int)(0xFFFFFFFFu - (unsigned)(key & 0xFFFFFFFFull));

    float4 g = ((const float4*)gt_boxes)[b * MM + m];
    int label = gt_labels[b * MM + m];

    const float* p; int HW, W, q; float st;
    if (n < N0)           { p = p0; HW = N0; W = 160; q = n;             st = strides[0]; }
    else if (n < N0 + N1) { p = p1; HW = N1; W = 80;  q = n - N0;        st = strides[1]; }
    else                  { p = p2; HW = N2; W = 40;  q = n - (N0 + N1); st = strides[2]; }
    int qy = q / W;
    float ax = (float)(q - qy * W) + 0.5f;
    float ay = (float)qy + 0.5f;

    const float* base = p + (size_t)b * 144 * HW + q;
    float x0 = base[(size_t)lane * HW];          // channels 0-31  (sides 0,1)
    float x1 = base[(size_t)(lane + 32) * HW];   // channels 32-63 (sides 2,3)

    float e0 = __expf(x0), e1 = __expf(x1);
#pragma unroll
    for (int d = 1; d < 16; d <<= 1) {
        e0 += __shfl_xor_sync(0xffffffffu, e0, d);
        e1 += __shfl_xor_sync(0xffffffffu, e1, d);
    }
    float lse0 = __logf(__shfl_sync(0xffffffffu, e0, 0));
    float lse1 = __logf(__shfl_sync(0xffffffffu, e0, 16));
    float lse2 = __logf(__shfl_sync(0xffffffffu, e1, 0));
    float lse3 = __logf(__shfl_sync(0xffffffffu, e1, 16));

    float t0 = fminf(fmaxf(ax - g.x / st, 0.f), 14.99f);
    float t1 = fminf(fmaxf(ay - g.y / st, 0.f), 14.99f);
    float t2 = fminf(fmaxf(g.z / st - ax, 0.f), 14.99f);
    float t3 = fminf(fmaxf(g.w / st - ay, 0.f), 14.99f);
    int l0 = (int)t0, l1 = (int)t1, l2 = (int)t2, l3 = (int)t3;
    int r0 = min(l0 + 1, 15), r1 = min(l1 + 1, 15), r2 = min(l2 + 1, 15), r3 = min(l3 + 1, 15);

    float xl0 = __shfl_sync(0xffffffffu, x0, l0);
    float xr0 = __shfl_sync(0xffffffffu, x0, r0);
    float xl1 = __shfl_sync(0xffffffffu, x0, 16 + l1);
    float xr1 = __shfl_sync(0xffffffffu, x0, 16 + r1);
    float xl2 = __shfl_sync(0xffffffffu, x1, l2);
    float xr2 = __shfl_sync(0xffffffffu, x1, r2);
    float xl3 = __shfl_sync(0xffffffffu, x1, 16 + l3);
    float xr3 = __shfl_sync(0xffffffffu, x1, 16 + r3);

    if (lane == 0) {
        float dfl =
            ((float)r0 - t0) * (lse0 - xl0) + (t0 - (float)l0) * (lse0 - xr0) +
            ((float)r1 - t1) * (lse1 - xl1) + (t1 - (float)l1) * (lse1 - xr1) +
            ((float)r2 - t2) * (lse2 - xl2) + (t2 - (float)l2) * (lse2 - xr2) +
            ((float)r3 - t3) * (lse3 - xl3) + (t3 - (float)l3) * (lse3 - xr3);

        float4 pbv = g_pb[idx];
        float boxl = 1.f - ciou_f(pbv.x, pbv.y, pbv.z, pbv.w, g.x, g.y, g.z, g.w);
        float pcv = base[(size_t)(64 + label) * HW];

        atomicAdd(&g_box[b], boxl);
        atomicAdd(&g_dfl[b], dfl);
        atomicAdd(&g_clspos[b], pcv * score);
    }
}

// ================= k_final: tiny combine after the join =================
__global__ void __launch_bounds__(256) k_final(float* __restrict__ out) {
    int tid = threadIdx.x;
    int w = tid >> 5, l = tid & 31;
    __shared__ double s8[8];
    if (w < 8) {
        double sp = 0.0;
        for (int j = l; j < SP_BLK; j += 32) sp += g_sp_part[w * SP_BLK + j];
#pragma unroll
        for (int d = 16; d > 0; d >>= 1) sp += __shfl_down_sync(0xffffffffu, sp, d);
        if (l == 0) {
            int cnt = g_fgcnt[w];
            double has = cnt > 0 ? 1.0 : 0.0;
            double nf = cnt > 0 ? (double)cnt : 1.0;
            double bl = (double)g_box[w] / nf;
            double dl = (double)g_dfl[w] / (nf * 4.0);
            double cl = (sp - (double)g_clspos[w]) / (double)NTOT;
            s8[w] = (7.5 * bl + 0.5 * cl + 1.5 * dl) * has;
        }
    }
    __syncthreads();
    if (tid == 0) {
        double total = 0.0;
#pragma unroll
        for (int b = 0; b < BB; b++) total += s8[b];
        out[0] = (float)total;
    }
}

// ---------------- launch: fork-join; fg hidden under softplus ----------------
extern "C" void kernel_launch(void* const* d_in, const int* in_sizes, int n_in,
                              void* d_out, int out_size) {
    const float* p0 = (const float*)d_in[0];
    const float* p1 = (const float*)d_in[1];
    const float* p2 = (const float*)d_in[2];
    const float* gtb = (const float*)d_in[3];
    const int* gtl = (const int*)d_in[4];
    const float* strides = (const float*)d_in[5];
    float* out = (float*)d_out;

    static cudaStream_t s_side = nullptr;
    static cudaEvent_t ev_fork = nullptr, ev_join = nullptr;
    if (s_side == nullptr) {
        cudaStreamCreateWithFlags(&s_side, cudaStreamNonBlocking);
        cudaEventCreateWithFlags(&ev_fork, cudaEventDisableTiming);
        cudaEventCreateWithFlags(&ev_join, cudaEventDisableTiming);
    }

    // fork: side branch runs the softplus stream (unrolled, 86MB)
    cudaEventRecord(ev_fork, 0);
    cudaStreamWaitEvent(s_side, ev_fork, 0);
    k_softplus<<<dim3(SP_BLK, BB), 256, 0, s_side>>>(p0, p1, p2);
    cudaEventRecord(ev_join, s_side);

    // main branch: decode -> assign -> fg (all independent of softplus)
    k_decode<<<dim3(DEC_BLK, BB), 256>>>(p0, p1, p2, strides);
    k_assign<<<BB * MM, 256>>>(p0, p1, p2, gtb, gtl, strides);
    k_fg<<<FG_BLK, 256>>>(p0, p1, p2, gtb, gtl, strides);

    // join: only the trivial final combine is exposed
    cudaStreamWaitEvent(0, ev_join, 0);
    k_final<<<1, 256>>>(out);
}

// round 16
// speedup vs baseline: 1.6680x; 1.0724x over previous
#include <cuda_runtime.h>
#include <cstdint>

#define BB 8
#define MM 32
#define NCLS 80
#define N0 25600
#define N1 6400
#define N2 1600
#define NTOT 33600
#define TOPKK 10
#define QTOT 8400            // NTOT/4 (float4 anchors per image)
#define DEC_BLK 33           // decode blocks per image
#define SP_BLK 128           // total softplus slices per image
#define SP1 64               // sp slices per image fused into K1
#define SP2 64               // sp slices per image fused into K2
#define S0 512000            // 80*25600/4 float4 per image (p0 cls)
#define S1 128000
#define SP_TOT 672000
#define FG_MAX 2560
#define FG_BLK 320           // 2560 fg warps / 8 warps-per-block

// ---------------- scratch ----------------
__device__ float4 g_pb[BB * NTOT];                 // decoded pred boxes (image units)
__device__ unsigned long long g_best[BB * NTOT];   // (score<<32 | ~m)
__device__ double g_sp_part[BB * SP_BLK];          // softplus slice partials
__device__ int g_fglist[FG_MAX];
__device__ int g_fgtot;
__device__ int g_fgcnt[BB];
__device__ float g_box[BB], g_dfl[BB], g_clspos[BB];
__device__ unsigned g_done;

// ---------------- helpers ----------------
__device__ __forceinline__ float ciou_f(float b1x1, float b1y1, float b1x2, float b1y2,
                                        float b2x1, float b2y1, float b2x2, float b2y2) {
    const float eps = 1e-7f;
    float w1 = b1x2 - b1x1, h1 = b1y2 - b1y1;
    float w2 = b2x2 - b2x1, h2 = b2y2 - b2y1;
    float iw = fminf(b1x2, b2x2) - fmaxf(b1x1, b2x1);
    float ih = fminf(b1y2, b2y2) - fmaxf(b1y1, b2y1);
    float inter = fmaxf(iw, 0.f) * fmaxf(ih, 0.f);
    float uni = w1 * h1 + w2 * h2 - inter + eps;
    float iou = inter / uni;
    float cw = fmaxf(b1x2, b2x2) - fminf(b1x1, b2x1);
    float ch = fmaxf(b1y2, b2y2) - fminf(b1y1, b2y1);
    float c2 = cw * cw + ch * ch + eps;
    float dx = b2x1 + b2x2 - b1x1 - b1x2;
    float dy = b2y1 + b2y2 - b1y1 - b1y2;
    float rho2 = (dx * dx + dy * dy) * 0.25f;
    float dat = atanf(w2 / (h2 + eps)) - atanf(w1 / (h1 + eps));
    float v = 0.4052847345693511f * dat * dat;
    float alpha = v / (v - iou + (1.f + eps));
    return iou - (rho2 / c2 + v * alpha);
}

__device__ __forceinline__ unsigned long long umax64(unsigned long long a, unsigned long long b) {
    return a > b ? a : b;
}

__device__ __forceinline__ unsigned long long warp_max64(unsigned long long v) {
#pragma unroll
    for (int d = 16; d > 0; d >>= 1)
        v = umax64(v, __shfl_down_sync(0xffffffffu, v, d));
    return v;
}

// softplus slice worker: slice index sblk in [0, SP_BLK), image b
__device__ __forceinline__ void sp_slice(const float* p0, const float* p1, const float* p2,
                                         int b, int sblk, int tid) {
    const float4* f40 = (const float4*)(p0 + ((size_t)b * 144 + 64) * N0);
    const float4* f41 = (const float4*)(p1 + ((size_t)b * 144 + 64) * N1);
    const float4* f42 = (const float4*)(p2 + ((size_t)b * 144 + 64) * N2);
    float acc = 0.f;
    float P0 = 1.f, P1 = 1.f, P2 = 1.f, P3 = 1.f;
    int cnt = 0;
    for (int i = sblk * 256 + tid; i < SP_TOT; i += SP_BLK * 256) {
        float4 v;
        if (i < S0)           v = f40[i];
        else if (i < S0 + S1) v = f41[i - S0];
        else                  v = f42[i - S0 - S1];
        acc += fmaxf(v.x, 0.f) + fmaxf(v.y, 0.f) + fmaxf(v.z, 0.f) + fmaxf(v.w, 0.f);
        P0 *= 1.f + __expf(-fabsf(v.x));
        P1 *= 1.f + __expf(-fabsf(v.y));
        P2 *= 1.f + __expf(-fabsf(v.z));
        P3 *= 1.f + __expf(-fabsf(v.w));
        if ((++cnt & 7) == 0) {   // flush every 32 terms (each <= 2)
            acc += __logf((P0 * P1) * (P2 * P3));
            P0 = P1 = P2 = P3 = 1.f;
        }
    }
    acc += __logf((P0 * P1) * (P2 * P3));

    __shared__ double sred[256];
    sred[tid] = (double)acc;
    __syncthreads();
    for (int s = 128; s > 0; s >>= 1) {
        if (tid < s) sred[tid] += sred[tid + s];
        __syncthreads();
    }
    if (tid == 0) g_sp_part[b * SP_BLK + sblk] = sred[0];
}

// ============ K1: decode blocks + softplus slices 0..SP1-1 (co-resident) ============
__global__ void __launch_bounds__(256) k_phase1(
        const float* __restrict__ p0, const float* __restrict__ p1,
        const float* __restrict__ p2, const float* __restrict__ strides) {
    int b = blockIdx.y;
    int tid = threadIdx.x;

    if (blockIdx.x == 0 && tid == 0) {
        g_fgcnt[b] = 0; g_box[b] = 0.f; g_dfl[b] = 0.f; g_clspos[b] = 0.f;
        if (b == 0) { g_done = 0u; g_fgtot = 0; }
    }

    if (blockIdx.x < DEC_BLK) {
        // ---------------- decode: 4 anchors per thread (R3 verbatim) ----------------
        int j = blockIdx.x * 256 + tid;
        if (j >= QTOT) return;
        const float* p; int HW, W, q4, noff; float st;
        if (j < 6400)      { p = p0; HW = N0; W = 160; q4 = j;        noff = 0;       st = strides[0]; }
        else if (j < 8000) { p = p1; HW = N1; W = 80;  q4 = j - 6400; noff = N0;      st = strides[1]; }
        else               { p = p2; HW = N2; W = 40;  q4 = j - 8000; noff = N0 + N1; st = strides[2]; }
        int q = q4 * 4;
        float ay = (float)(q / W) + 0.5f;
        float ax = (float)(q % W) + 0.5f;

        const float* pb = p + (size_t)b * 144 * HW + q;
        float4 out[4];
#pragma unroll
        for (int k = 0; k < 4; k++) {
            float se0 = 0.f, se1 = 0.f, se2 = 0.f, se3 = 0.f;
            float sw0 = 0.f, sw1 = 0.f, sw2 = 0.f, sw3 = 0.f;
#pragma unroll
            for (int r = 0; r < 16; r++) {
                float4 v = *(const float4*)(pb + (size_t)(k * 16 + r) * HW);
                float e0 = __expf(v.x), e1 = __expf(v.y), e2 = __expf(v.z), e3 = __expf(v.w);
                float fr = (float)r;
                se0 += e0; sw0 = fmaf(e0, fr, sw0);
                se1 += e1; sw1 = fmaf(e1, fr, sw1);
                se2 += e2; sw2 = fmaf(e2, fr, sw2);
                se3 += e3; sw3 = fmaf(e3, fr, sw3);
            }
            float d0 = sw0 / se0, d1 = sw1 / se1, d2 = sw2 / se2, d3 = sw3 / se3;
            if (k == 0) { out[0].x = (ax - d0) * st;        out[1].x = (ax + 1.f - d1) * st;
                          out[2].x = (ax + 2.f - d2) * st;  out[3].x = (ax + 3.f - d3) * st; }
            if (k == 1) { out[0].y = (ay - d0) * st; out[1].y = (ay - d1) * st;
                          out[2].y = (ay - d2) * st; out[3].y = (ay - d3) * st; }
            if (k == 2) { out[0].z = (ax + d0) * st;        out[1].z = (ax + 1.f + d1) * st;
                          out[2].z = (ax + 2.f + d2) * st;  out[3].z = (ax + 3.f + d3) * st; }
            if (k == 3) { out[0].w = (ay + d0) * st; out[1].w = (ay + d1) * st;
                          out[2].w = (ay + d2) * st; out[3].w = (ay + d3) * st; }
        }
        int base = b * NTOT + noff + q;
#pragma unroll
        for (int a = 0; a < 4; a++) {
            g_pb[base + a] = out[a];
            g_best[base + a] = 0xFFFFFFFFull;   // sentinel: score 0, m = 0
        }
    } else {
        sp_slice(p0, p1, p2, b, blockIdx.x - DEC_BLK, tid);   // slices 0..SP1-1
    }
}

// ====== K2: assign blocks (0..255) + softplus slices SP1..127 (co-resident) ======
__global__ void __launch_bounds__(256) k_phase2(
        const float* __restrict__ p0, const float* __restrict__ p1,
        const float* __restrict__ p2,
        const float* __restrict__ gt_boxes, const int* __restrict__ gt_labels,
        const float* __restrict__ strides) {
    int tid = threadIdx.x;

    if (blockIdx.x >= BB * MM) {
        int g = blockIdx.x - BB * MM;
        sp_slice(p0, p1, p2, g / SP2, SP1 + (g % SP2), tid);
        return;
    }

    __shared__ unsigned long long sh_keys[256 * TOPKK];
    __shared__ unsigned long long sh_w[8];
    __shared__ unsigned long long sh_best;
    __shared__ float sh_fw[8];
    __shared__ float sh_cmax;

    int b = blockIdx.x >> 5, m = blockIdx.x & 31;
    int wid = tid >> 5, lid = tid & 31;

    float gx1 = gt_boxes[(b * MM + m) * 4 + 0];
    float gy1 = gt_boxes[(b * MM + m) * 4 + 1];
    float gx2 = gt_boxes[(b * MM + m) * 4 + 2];
    float gy2 = gt_boxes[(b * MM + m) * 4 + 3];
    int label = gt_labels[b * MM + m];

    float tv[TOPKK]; int tn[TOPKK];
#pragma unroll
    for (int jj = 0; jj < TOPKK; jj++) { tv[jj] = 0.f; tn[jj] = 0x7FFFFFFF; }
    float cmax = 0.f;

#pragma unroll
    for (int lvl = 0; lvl < 3; lvl++) {
        const float* p; int HW, W, noff; float st;
        if (lvl == 0)      { p = p0; HW = N0; W = 160; noff = 0;       st = strides[0]; }
        else if (lvl == 1) { p = p1; HW = N1; W = 80;  noff = N0;      st = strides[1]; }
        else               { p = p2; HW = N2; W = 40;  noff = N0 + N1; st = strides[2]; }

        float inv = 1.f / st;
        int x0 = max(0, (int)(gx1 * inv - 0.5f) - 1);
        int x1 = min(W - 1, (int)(gx2 * inv - 0.5f) + 1);
        int y0 = max(0, (int)(gy1 * inv - 0.5f) - 1);
        int y1 = min(W - 1, (int)(gy2 * inv - 0.5f) + 1);
        int rw = x1 - x0 + 1, rh = y1 - y0 + 1;
        if (rw <= 0 || rh <= 0) continue;
        int tot = rw * rh;
        const float* pcl = p + ((size_t)b * 144 + 64 + label) * HW;

        for (int i = tid; i < tot; i += 256) {
            int qx = x0 + i % rw;
            int qy = y0 + i / rw;
            float ax = ((float)qx + 0.5f) * st;
            float ay = ((float)qy + 0.5f) * st;
            if (ax < gx1 || ax > gx2 || ay < gy1 || ay > gy2) continue;
            int q = qy * W + qx;
            int n = noff + q;
            float4 pbv = g_pb[b * NTOT + n];
            float iou = fmaxf(ciou_f(pbv.x, pbv.y, pbv.z, pbv.w, gx1, gy1, gx2, gy2), 0.f);
            float ps = 1.f / (1.f + __expf(-pcl[q]));
            float i2 = iou * iou;
            float align = ps * (i2 * i2 * i2);
            cmax = fmaxf(cmax, align);
            if (iou > 0.1f && align > 0.f &&
                ((align > tv[TOPKK - 1]) ||
                 (align == tv[TOPKK - 1] && n < tn[TOPKK - 1]))) {
                float cv = align; int cn = n;
#pragma unroll
                for (int jj = 0; jj < TOPKK; jj++) {
                    bool bt = (cv > tv[jj]) || (cv == tv[jj] && cn < tn[jj]);
                    float nv = bt ? cv : tv[jj];  int nn = bt ? cn : tn[jj];
                    cv = bt ? tv[jj] : cv;        cn = bt ? tn[jj] : cn;
                    tv[jj] = nv;                  tn[jj] = nn;
                }
            }
        }
    }

#pragma unroll
    for (int d = 16; d > 0; d >>= 1)
        cmax = fmaxf(cmax, __shfl_down_sync(0xffffffffu, cmax, d));
    if (lid == 0) sh_fw[wid] = cmax;
    __syncthreads();
    if (tid == 0) {
        float c = sh_fw[0];
#pragma unroll
        for (int w = 1; w < 8; w++) c = fmaxf(c, sh_fw[w]);
        sh_cmax = c;
    }

#pragma unroll
    for (int jj = 0; jj < TOPKK; jj++) {
        unsigned long long key = 0ull;
        if (tv[jj] > 0.f)
            key = ((unsigned long long)__float_as_uint(tv[jj]) << 32) |
                  (unsigned long long)(0xFFFFFFFFu - (unsigned)tn[jj]);
        sh_keys[tid * TOPKK + jj] = key;
    }
    __syncthreads();
    float colmax = sh_cmax;

    for (int iter = 0; iter < TOPKK; iter++) {
        unsigned long long loc = 0ull;
#pragma unroll
        for (int jj = 0; jj < TOPKK; jj++)
            loc = umax64(loc, sh_keys[tid + jj * 256]);
        loc = warp_max64(loc);
        if (lid == 0) sh_w[wid] = loc;
        __syncthreads();
        if (tid == 0) {
            unsigned long long v = sh_w[0];
#pragma unroll
            for (int w = 1; w < 8; w++) v = umax64(v, sh_w[w]);
            sh_best = v;
        }
        __syncthreads();
        unsigned long long bestk = sh_best;
        if (bestk == 0ull) break;
#pragma unroll
        for (int jj = 0; jj < TOPKK; jj++)
            if (sh_keys[tid * TOPKK + jj] == bestk) sh_keys[tid * TOPKK + jj] = 0ull;
        if (tid == 0) {
            float val = __uint_as_float((unsigned)(bestk >> 32));
            int n = (int)(0xFFFFFFFFu - (unsigned)(bestk & 0xFFFFFFFFull));
            float norm = val / (colmax + 1e-9f);
            unsigned long long okey =
                ((unsigned long long)__float_as_uint(norm) << 32) |
                (unsigned long long)(0xFFFFFFFFu - (unsigned)m);
            int gidx = b * NTOT + n;
            unsigned long long old = atomicMax(&g_best[gidx], okey);
            if (old == 0xFFFFFFFFull) {     // first writer -> compaction for free
                atomicAdd(&g_fgcnt[b], 1);
                int pos = atomicAdd(&g_fgtot, 1);
                g_fglist[pos] = gidx;
            }
        }
        __syncthreads();
    }
}

// ===== K3: one warp per fg anchor (lane-parallel DFL) + last-block final combine =====
__global__ void __launch_bounds__(256) k_fg(
        const float* __restrict__ p0, const float* __restrict__ p1,
        const float* __restrict__ p2,
        const float* __restrict__ gt_boxes, const int* __restrict__ gt_labels,
        const float* __restrict__ strides, float* __restrict__ out) {
    int tid = threadIdx.x;
    int lane = tid & 31;
    int i = blockIdx.x * 8 + (tid >> 5);

    if (i < g_fgtot) {
        int idx = g_fglist[i];
        unsigned long long key = g_best[idx];
        float score = __uint_as_float((unsigned)(key >> 32));
        int b = idx / NTOT, n = idx - (idx / NTOT) * NTOT;
        int m = (int)(0xFFFFFFFFu - (unsigned)(key & 0xFFFFFFFFull));

        float4 g = ((const float4*)gt_boxes)[b * MM + m];
        int label = gt_labels[b * MM + m];

        const float* p; int HW, W, q; float st;
        if (n < N0)           { p = p0; HW = N0; W = 160; q = n;             st = strides[0]; }
        else if (n < N0 + N1) { p = p1; HW = N1; W = 80;  q = n - N0;        st = strides[1]; }
        else                  { p = p2; HW = N2; W = 40;  q = n - (N0 + N1); st = strides[2]; }
        int qy = q / W;
        float ax = (float)(q - qy * W) + 0.5f;
        float ay = (float)qy + 0.5f;

        const float* base = p + (size_t)b * 144 * HW + q;
        float x0 = base[(size_t)lane * HW];          // channels 0-31  (sides 0,1)
        float x1 = base[(size_t)(lane + 32) * HW];   // channels 32-63 (sides 2,3)

        float e0 = __expf(x0), e1 = __expf(x1);
#pragma unroll
        for (int d = 1; d < 16; d <<= 1) {
            e0 += __shfl_xor_sync(0xffffffffu, e0, d);
            e1 += __shfl_xor_sync(0xffffffffu, e1, d);
        }
        float lse0 = __logf(__shfl_sync(0xffffffffu, e0, 0));
        float lse1 = __logf(__shfl_sync(0xffffffffu, e0, 16));
        float lse2 = __logf(__shfl_sync(0xffffffffu, e1, 0));
        float lse3 = __logf(__shfl_sync(0xffffffffu, e1, 16));

        float t0 = fminf(fmaxf(ax - g.x / st, 0.f), 14.99f);
        float t1 = fminf(fmaxf(ay - g.y / st, 0.f), 14.99f);
        float t2 = fminf(fmaxf(g.z / st - ax, 0.f), 14.99f);
        float t3 = fminf(fmaxf(g.w / st - ay, 0.f), 14.99f);
        int l0 = (int)t0, l1 = (int)t1, l2 = (int)t2, l3 = (int)t3;
        int r0 = min(l0 + 1, 15), r1 = min(l1 + 1, 15), r2 = min(l2 + 1, 15), r3 = min(l3 + 1, 15);

        float xl0 = __shfl_sync(0xffffffffu, x0, l0);
        float xr0 = __shfl_sync(0xffffffffu, x0, r0);
        float xl1 = __shfl_sync(0xffffffffu, x0, 16 + l1);
        float xr1 = __shfl_sync(0xffffffffu, x0, 16 + r1);
        float xl2 = __shfl_sync(0xffffffffu, x1, l2);
        float xr2 = __shfl_sync(0xffffffffu, x1, r2);
        float xl3 = __shfl_sync(0xffffffffu, x1, 16 + l3);
        float xr3 = __shfl_sync(0xffffffffu, x1, 16 + r3);

        if (lane == 0) {
            float dfl =
                ((float)r0 - t0) * (lse0 - xl0) + (t0 - (float)l0) * (lse0 - xr0) +
                ((float)r1 - t1) * (lse1 - xl1) + (t1 - (float)l1) * (lse1 - xr1) +
                ((float)r2 - t2) * (lse2 - xl2) + (t2 - (float)l2) * (lse2 - xr2) +
                ((float)r3 - t3) * (lse3 - xl3) + (t3 - (float)l3) * (lse3 - xr3);

            float4 pbv = g_pb[idx];
            float boxl = 1.f - ciou_f(pbv.x, pbv.y, pbv.z, pbv.w, g.x, g.y, g.z, g.w);
            float pcv = base[(size_t)(64 + label) * HW];

            atomicAdd(&g_box[b], boxl);
            atomicAdd(&g_dfl[b], dfl);
            atomicAdd(&g_clspos[b], pcv * score);
        }
    }

    // ---- completion detection: last block computes the final scalar ----
    __shared__ bool s_last;
    __syncthreads();
    if (tid == 0) {
        __threadfence();
        unsigned v = atomicAdd(&g_done, 1u);
        s_last = (v == (unsigned)(gridDim.x - 1));
    }
    __syncthreads();
    if (!s_last) return;

    int w = tid >> 5, l = tid & 31;
    __shared__ double s8[8];
    if (w < 8) {
        double sp = 0.0;
        for (int j = l; j < SP_BLK; j += 32) sp += g_sp_part[w * SP_BLK + j];
#pragma unroll
        for (int d = 16; d > 0; d >>= 1) sp += __shfl_down_sync(0xffffffffu, sp, d);
        if (l == 0) {
            int cnt = g_fgcnt[w];
            double has = cnt > 0 ? 1.0 : 0.0;
            double nf = cnt > 0 ? (double)cnt : 1.0;
            double bl = (double)g_box[w] / nf;
            double dl = (double)g_dfl[w] / (nf * 4.0);
            double cl = (sp - (double)g_clspos[w]) / (double)NTOT;
            s8[w] = (7.5 * bl + 0.5 * cl + 1.5 * dl) * has;
        }
    }
    __syncthreads();
    if (tid == 0) {
        double total = 0.0;
#pragma unroll
        for (int b = 0; b < BB; b++) total += s8[b];
        out[0] = (float)total;
    }
}

// ---------------- launch: 3-node linear graph, co-residence inside kernels ----------------
extern "C" void kernel_launch(void* const* d_in, const int* in_sizes, int n_in,
                              void* d_out, int out_size) {
    const float* p0 = (const float*)d_in[0];
    const float* p1 = (const float*)d_in[1];
    const float* p2 = (const float*)d_in[2];
    const float* gtb = (const float*)d_in[3];
    const int* gtl = (const int*)d_in[4];
    const float* strides = (const float*)d_in[5];
    float* out = (float*)d_out;

    k_phase1<<<dim3(DEC_BLK + SP1, BB), 256>>>(p0, p1, p2, strides);
    k_phase2<<<BB * MM + SP2 * BB, 256>>>(p0, p1, p2, gtb, gtl, strides);
    k_fg<<<FG_BLK, 256>>>(p0, p1, p2, gtb, gtl, strides, out);
}